// round 15
// baseline (speedup 1.0000x reference)
#include <cuda_runtime.h>
#include <cuda_fp16.h>
#include <mma.h>
#include <math.h>

using namespace nvcuda;

// Problem-fixed capacities (dataset constants)
#define NCAP 100000
#define NPAD (NCAP + 128)
#define ECAP 1600000
#define ITERS 5

struct __align__(8) EdgeRec { int src; float w; };
typedef unsigned long long u64;
typedef unsigned int u32;

// ---- static device scratch (no allocation allowed) ----
// zero region: [counts | cursor | total]
__device__ int     g_zero[2 * NCAP + 4];
__device__ int     g_rowoff[NCAP];
__device__ int     g_rowend[NCAP];
__device__ float   g_dis[NCAP];
__device__ EdgeRec g_edges[ECAP];
__device__ float   g_aggx[NCAP * 3];
__device__ float4  g_t[NCAP * 16];
__device__ float4  g_u[NCAP * 16];
__device__ float4  g_v[NCAP * 16];
// fp16 mirrors, padded (64 halfs = 8 uint4 per node)
__device__ uint4   g_t16[NPAD * 8];
__device__ uint4   g_u16[NPAD * 8];
__device__ uint4   g_v16[NPAD * 8];
// fp16 weights: Wr_t, W11, W12, W21, W22 (each 64x64)
__device__ uint4   g_w16[5 * 4096 / 8];

// ---- packed fp32x2 helpers ----
__device__ __forceinline__ u64 pack2(float x, float y) {
    u64 r; asm("mov.b64 %0, {%1, %2};" : "=l"(r) : "f"(x), "f"(y)); return r;
}
__device__ __forceinline__ void unpack2(u64 v, float& x, float& y) {
    asm("mov.b64 {%0, %1}, %2;" : "=f"(x), "=f"(y) : "l"(v));
}
__device__ __forceinline__ void ffma2(u64& d, u64 a, u64 b) {
    asm("fma.rn.f32x2 %0, %1, %2, %0;" : "+l"(d) : "l"(a), "l"(b));
}

// ---- fp16 pack/unpack ----
__device__ __forceinline__ float2 h2f(u32 q) {
    __half2 h = *reinterpret_cast<__half2*>(&q);
    return __half22float2(h);
}
__device__ __forceinline__ u32 f2h(float x, float y) {
    __half2 h = __floats2half2_rn(x, y);
    return *reinterpret_cast<u32*>(&h);
}

// accumulate one fp16x8 feature chunk (uint4) scaled by wt into A[8]
__device__ __forceinline__ void acc_e(uint4 q, float wt, float* A) {
    float2 fa = h2f(q.x), fb = h2f(q.y);
    float2 fc = h2f(q.z), fd = h2f(q.w);
    A[0] = fmaf(wt, fa.x, A[0]); A[1] = fmaf(wt, fa.y, A[1]);
    A[2] = fmaf(wt, fb.x, A[2]); A[3] = fmaf(wt, fb.y, A[3]);
    A[4] = fmaf(wt, fc.x, A[4]); A[5] = fmaf(wt, fc.y, A[5]);
    A[6] = fmaf(wt, fd.x, A[6]); A[7] = fmaf(wt, fd.y, A[7]);
}

// =============== graph setup kernels ===============

__global__ void k_count(const int* __restrict__ dst, int E, int* __restrict__ counts) {
    int i = blockIdx.x * blockDim.x + threadIdx.x;
    if (i < E) atomicAdd(&counts[dst[i]], 1);
}

__global__ void k_setup2(const int* __restrict__ counts, float* __restrict__ dis,
                         int* __restrict__ rowoff, int* __restrict__ rowend,
                         int* __restrict__ total, int N,
                         const float* __restrict__ Wr, const float* __restrict__ W11,
                         const float* __restrict__ W12, const float* __restrict__ W21,
                         const float* __restrict__ W22, __half* __restrict__ w16) {
    int i = blockIdx.x * blockDim.x + threadIdx.x;
    if (i < 4096) {
        w16[i]            = __float2half_rn(Wr[i]);
        w16[4096 + i]     = __float2half_rn(W11[i]);
        w16[2 * 4096 + i] = __float2half_rn(W12[i]);
        w16[3 * 4096 + i] = __float2half_rn(W21[i]);
        w16[4 * 4096 + i] = __float2half_rn(W22[i]);
    }
    if (i < N) {
        int c = counts[i];
        dis[i] = rsqrtf((float)(c + 1));
        int off = atomicAdd(total, c);
        rowoff[i] = off;
        rowend[i] = off + c;
    }
}

__global__ void k_fill(const int* __restrict__ srcA, const int* __restrict__ dstA, int E,
                       const int* __restrict__ rowoff, int* __restrict__ cursor,
                       const float* __restrict__ dis, EdgeRec* __restrict__ edges) {
    int i = blockIdx.x * blockDim.x + threadIdx.x;
    if (i >= E) return;
    int s = srcA[i], d = dstA[i];
    int pos = rowoff[d] + atomicAdd(&cursor[d], 1);
    EdgeRec r;
    r.src = s;
    r.w = dis[s] * dis[d];
    edges[pos] = r;
}

// fused: aggx = agg(x) + projection
__global__ void k_aggx_proj(const float* __restrict__ x, const EdgeRec* __restrict__ edges,
                            const int* __restrict__ rowoff, const int* __restrict__ rowend,
                            const float* __restrict__ dis,
                            const float* __restrict__ Wp, const float* __restrict__ bp,
                            float* __restrict__ aggx, float* __restrict__ t,
                            __half* __restrict__ t16, int N) {
    int node = blockIdx.x * 8 + (threadIdx.x >> 5);
    int lane = threadIdx.x & 31;
    if (node >= N) return;
    float a0 = 0.f, a1 = 0.f, a2 = 0.f;
    int e0 = rowoff[node], e1 = rowend[node];
    for (int e = e0 + lane; e < e1; e += 32) {
        EdgeRec r = edges[e];
        const float* xp = x + (size_t)r.src * 3;
        a0 = fmaf(r.w, __ldg(xp), a0);
        a1 = fmaf(r.w, __ldg(xp + 1), a1);
        a2 = fmaf(r.w, __ldg(xp + 2), a2);
    }
    if (lane == 0) {
        float dv = dis[node];
        float sw = dv * dv;
        const float* xp = x + (size_t)node * 3;
        a0 = fmaf(sw, xp[0], a0);
        a1 = fmaf(sw, xp[1], a1);
        a2 = fmaf(sw, xp[2], a2);
    }
#pragma unroll
    for (int off = 16; off > 0; off >>= 1) {
        a0 += __shfl_xor_sync(0xffffffffu, a0, off);
        a1 += __shfl_xor_sync(0xffffffffu, a1, off);
        a2 += __shfl_xor_sync(0xffffffffu, a2, off);
    }
    if (lane == 0) {
        aggx[node * 3] = a0;
        aggx[node * 3 + 1] = a1;
        aggx[node * 3 + 2] = a2;
    }
#pragma unroll
    for (int jj = 0; jj < 2; jj++) {
        int j = 2 * lane + jj;
        float acc = bp[j];
        acc = fmaf(a0, Wp[j], acc);
        acc = fmaf(a1, Wp[64 + j], acc);
        acc = fmaf(a2, Wp[128 + j], acc);
        acc = fmaxf(acc, 0.f);
        t[(size_t)node * 64 + j] = acc;
        t16[(size_t)node * 64 + j] = __float2half_rn(acc);
    }
}

// =============== main aggregation: edge-parity split gather ===============
// 2 nodes per warp; per node, 16 lanes split into 2 groups of 8.
// Group g processes edges e0+g, e0+g+2, ... (parity split) -> per-stream
// serial chain halved. Each lane loads uint4 (16B); 8 lanes cover the 128B row.
// Groups combined via shfl_xor(8) at the end.
template <int RELU, int RES, int W32>
__global__ void __launch_bounds__(256) k_aggv(
    const uint4* __restrict__ U16, const EdgeRec* __restrict__ edges,
    const int* __restrict__ rowoff, const int* __restrict__ rowend,
    const float* __restrict__ dis,
    const float* __restrict__ bias, const float* __restrict__ res,
    float* __restrict__ out, uint4* __restrict__ out16, int N) {
    int tid = threadIdx.x;
    int warp = tid >> 5;
    int lane = tid & 31;
    int half = lane >> 4;
    int group = (lane >> 3) & 1;
    int sub = lane & 7;
    int node = blockIdx.x * 16 + warp * 2 + half;
    bool active = (node < N);
    int nodec = active ? node : (N - 1);

    float aA[8], aB[8];
#pragma unroll
    for (int j = 0; j < 8; j++) { aA[j] = 0.f; aB[j] = 0.f; }

    int e0 = rowoff[nodec];
    int e1 = active ? rowend[nodec] : e0;
    int e = e0 + group;

    // 8-deep body: edges e, e+2, ..., e+14 (one batch covers deg<=16 nodes)
    for (; e + 14 < e1; e += 16) {
        u64 er0 = *(const u64*)(edges + e);
        u64 er1 = *(const u64*)(edges + e + 2);
        u64 er2 = *(const u64*)(edges + e + 4);
        u64 er3 = *(const u64*)(edges + e + 6);
        u64 er4 = *(const u64*)(edges + e + 8);
        u64 er5 = *(const u64*)(edges + e + 10);
        u64 er6 = *(const u64*)(edges + e + 12);
        u64 er7 = *(const u64*)(edges + e + 14);
        int s0 = (int)(u32)er0; float w0 = __uint_as_float((u32)(er0 >> 32));
        int s1 = (int)(u32)er1; float w1 = __uint_as_float((u32)(er1 >> 32));
        int s2 = (int)(u32)er2; float w2 = __uint_as_float((u32)(er2 >> 32));
        int s3 = (int)(u32)er3; float w3 = __uint_as_float((u32)(er3 >> 32));
        int s4 = (int)(u32)er4; float w4 = __uint_as_float((u32)(er4 >> 32));
        int s5 = (int)(u32)er5; float w5 = __uint_as_float((u32)(er5 >> 32));
        int s6 = (int)(u32)er6; float w6 = __uint_as_float((u32)(er6 >> 32));
        int s7 = (int)(u32)er7; float w7 = __uint_as_float((u32)(er7 >> 32));
        uint4 q0 = U16[(size_t)s0 * 8 + sub];
        uint4 q1 = U16[(size_t)s1 * 8 + sub];
        uint4 q2 = U16[(size_t)s2 * 8 + sub];
        uint4 q3 = U16[(size_t)s3 * 8 + sub];
        uint4 q4 = U16[(size_t)s4 * 8 + sub];
        uint4 q5 = U16[(size_t)s5 * 8 + sub];
        uint4 q6 = U16[(size_t)s6 * 8 + sub];
        uint4 q7 = U16[(size_t)s7 * 8 + sub];
        acc_e(q0, w0, aA); acc_e(q1, w1, aB);
        acc_e(q2, w2, aA); acc_e(q3, w3, aB);
        acc_e(q4, w4, aA); acc_e(q5, w5, aB);
        acc_e(q6, w6, aA); acc_e(q7, w7, aB);
    }
    // 2-deep
    for (; e + 2 < e1; e += 4) {
        u64 er0 = *(const u64*)(edges + e);
        u64 er1 = *(const u64*)(edges + e + 2);
        int s0 = (int)(u32)er0; float w0 = __uint_as_float((u32)(er0 >> 32));
        int s1 = (int)(u32)er1; float w1 = __uint_as_float((u32)(er1 >> 32));
        uint4 q0 = U16[(size_t)s0 * 8 + sub];
        uint4 q1 = U16[(size_t)s1 * 8 + sub];
        acc_e(q0, w0, aA); acc_e(q1, w1, aB);
    }
    // singles
    for (; e < e1; e += 2) {
        u64 er = *(const u64*)(edges + e);
        int s = (int)(u32)er; float wv = __uint_as_float((u32)(er >> 32));
        uint4 q = U16[(size_t)s * 8 + sub];
        acc_e(q, wv, aA);
    }
    // self loop: group 0 only
    if (active && group == 0) {
        float dv = dis[node];
        float sw = dv * dv;
        uint4 q = U16[(size_t)node * 8 + sub];
        acc_e(q, sw, aB);
    }

    float o[8];
#pragma unroll
    for (int j = 0; j < 8; j++) o[j] = aA[j] + aB[j];
    // combine the two parity groups (xor 8 stays within the 16-lane half)
#pragma unroll
    for (int j = 0; j < 8; j++) o[j] += __shfl_xor_sync(0xffffffffu, o[j], 8);

    if (!active || group != 0) return;

    if (bias) {
        float4 b0 = ((const float4*)bias)[sub * 2];
        float4 b1 = ((const float4*)bias)[sub * 2 + 1];
        o[0] += b0.x; o[1] += b0.y; o[2] += b0.z; o[3] += b0.w;
        o[4] += b1.x; o[5] += b1.y; o[6] += b1.z; o[7] += b1.w;
    }
    if (RES) {
        float4 r0 = ((const float4*)res)[(size_t)node * 16 + sub * 2];
        float4 r1 = ((const float4*)res)[(size_t)node * 16 + sub * 2 + 1];
        o[0] += r0.x; o[1] += r0.y; o[2] += r0.z; o[3] += r0.w;
        o[4] += r1.x; o[5] += r1.y; o[6] += r1.z; o[7] += r1.w;
    }
    if (RELU) {
#pragma unroll
        for (int j = 0; j < 8; j++) o[j] = fmaxf(o[j], 0.f);
    }
    if (W32) {
        ((float4*)out)[(size_t)node * 16 + sub * 2] =
            make_float4(o[0], o[1], o[2], o[3]);
        ((float4*)out)[(size_t)node * 16 + sub * 2 + 1] =
            make_float4(o[4], o[5], o[6], o[7]);
    }
    {
        uint4 m;
        m.x = f2h(o[0], o[1]);
        m.y = f2h(o[2], o[3]);
        m.z = f2h(o[4], o[5]);
        m.w = f2h(o[6], o[7]);
        out16[(size_t)node * 8 + sub] = m;
    }
}

// =============== head kernels (fp32, optimized) ===============

// width-32 gather: warp per node, 4-deep unroll
__global__ void k_agg32(const float* __restrict__ u, const EdgeRec* __restrict__ edges,
                        const int* __restrict__ rowoff, const int* __restrict__ rowend,
                        const float* __restrict__ dis,
                        const float* __restrict__ bias, int relu,
                        float* __restrict__ out, int N) {
    int node = blockIdx.x * 8 + (threadIdx.x >> 5);
    int lane = threadIdx.x & 31;
    if (node >= N) return;
    float a0 = 0.f, a1 = 0.f, a2 = 0.f, a3 = 0.f;
    int e = rowoff[node], e1 = rowend[node];
    for (; e + 4 <= e1; e += 4) {
        u64 er0 = *(const u64*)(edges + e);
        u64 er1 = *(const u64*)(edges + e + 1);
        u64 er2 = *(const u64*)(edges + e + 2);
        u64 er3 = *(const u64*)(edges + e + 3);
        int s0 = (int)(u32)er0; float w0 = __uint_as_float((u32)(er0 >> 32));
        int s1 = (int)(u32)er1; float w1 = __uint_as_float((u32)(er1 >> 32));
        int s2 = (int)(u32)er2; float w2 = __uint_as_float((u32)(er2 >> 32));
        int s3 = (int)(u32)er3; float w3 = __uint_as_float((u32)(er3 >> 32));
        float f0 = u[(size_t)s0 * 32 + lane];
        float f1 = u[(size_t)s1 * 32 + lane];
        float f2 = u[(size_t)s2 * 32 + lane];
        float f3 = u[(size_t)s3 * 32 + lane];
        a0 = fmaf(w0, f0, a0);
        a1 = fmaf(w1, f1, a1);
        a2 = fmaf(w2, f2, a2);
        a3 = fmaf(w3, f3, a3);
    }
    for (; e < e1; e++) {
        u64 er = *(const u64*)(edges + e);
        int s = (int)(u32)er; float wv = __uint_as_float((u32)(er >> 32));
        a0 = fmaf(wv, u[(size_t)s * 32 + lane], a0);
    }
    float dv = dis[node];
    a1 = fmaf(dv * dv, u[(size_t)node * 32 + lane], a1);
    float acc = (a0 + a1) + (a2 + a3);
    if (bias) acc += bias[lane];
    if (relu) acc = fmaxf(acc, 0.f);
    out[(size_t)node * 32 + lane] = acc;
}

// width-8 gather: thread per node, float4 loads, 2-edge unroll
__global__ void k_agg8(const float* __restrict__ u, const EdgeRec* __restrict__ edges,
                       const int* __restrict__ rowoff, const int* __restrict__ rowend,
                       const float* __restrict__ dis,
                       const float* __restrict__ bias, int relu,
                       float* __restrict__ out, int N) {
    int node = blockIdx.x * blockDim.x + threadIdx.x;
    if (node >= N) return;
    float aA[8] = {0.f, 0.f, 0.f, 0.f, 0.f, 0.f, 0.f, 0.f};
    float aB[8] = {0.f, 0.f, 0.f, 0.f, 0.f, 0.f, 0.f, 0.f};
    int e = rowoff[node], e1 = rowend[node];
    const float4* U4 = (const float4*)u;
    for (; e + 2 <= e1; e += 2) {
        u64 er0 = *(const u64*)(edges + e);
        u64 er1 = *(const u64*)(edges + e + 1);
        int s0 = (int)(u32)er0; float w0 = __uint_as_float((u32)(er0 >> 32));
        int s1 = (int)(u32)er1; float w1 = __uint_as_float((u32)(er1 >> 32));
        float4 x0 = U4[(size_t)s0 * 2],     y0 = U4[(size_t)s0 * 2 + 1];
        float4 x1 = U4[(size_t)s1 * 2],     y1 = U4[(size_t)s1 * 2 + 1];
        aA[0] = fmaf(w0, x0.x, aA[0]); aA[1] = fmaf(w0, x0.y, aA[1]);
        aA[2] = fmaf(w0, x0.z, aA[2]); aA[3] = fmaf(w0, x0.w, aA[3]);
        aA[4] = fmaf(w0, y0.x, aA[4]); aA[5] = fmaf(w0, y0.y, aA[5]);
        aA[6] = fmaf(w0, y0.z, aA[6]); aA[7] = fmaf(w0, y0.w, aA[7]);
        aB[0] = fmaf(w1, x1.x, aB[0]); aB[1] = fmaf(w1, x1.y, aB[1]);
        aB[2] = fmaf(w1, x1.z, aB[2]); aB[3] = fmaf(w1, x1.w, aB[3]);
        aB[4] = fmaf(w1, y1.x, aB[4]); aB[5] = fmaf(w1, y1.y, aB[5]);
        aB[6] = fmaf(w1, y1.z, aB[6]); aB[7] = fmaf(w1, y1.w, aB[7]);
    }
    for (; e < e1; e++) {
        u64 er = *(const u64*)(edges + e);
        int s = (int)(u32)er; float wv = __uint_as_float((u32)(er >> 32));
        float4 x0 = U4[(size_t)s * 2], y0 = U4[(size_t)s * 2 + 1];
        aA[0] = fmaf(wv, x0.x, aA[0]); aA[1] = fmaf(wv, x0.y, aA[1]);
        aA[2] = fmaf(wv, x0.z, aA[2]); aA[3] = fmaf(wv, x0.w, aA[3]);
        aA[4] = fmaf(wv, y0.x, aA[4]); aA[5] = fmaf(wv, y0.y, aA[5]);
        aA[6] = fmaf(wv, y0.z, aA[6]); aA[7] = fmaf(wv, y0.w, aA[7]);
    }
    {
        float dv = dis[node];
        float sw = dv * dv;
        float4 x0 = U4[(size_t)node * 2], y0 = U4[(size_t)node * 2 + 1];
        aB[0] = fmaf(sw, x0.x, aB[0]); aB[1] = fmaf(sw, x0.y, aB[1]);
        aB[2] = fmaf(sw, x0.z, aB[2]); aB[3] = fmaf(sw, x0.w, aB[3]);
        aB[4] = fmaf(sw, y0.x, aB[4]); aB[5] = fmaf(sw, y0.y, aB[5]);
        aB[6] = fmaf(sw, y0.z, aB[6]); aB[7] = fmaf(sw, y0.w, aB[7]);
    }
    float4 o0, o1;
    o0.x = aA[0] + aB[0]; o0.y = aA[1] + aB[1];
    o0.z = aA[2] + aB[2]; o0.w = aA[3] + aB[3];
    o1.x = aA[4] + aB[4]; o1.y = aA[5] + aB[5];
    o1.z = aA[6] + aB[6]; o1.w = aA[7] + aB[7];
    if (bias) {
        float4 b0 = ((const float4*)bias)[0];
        float4 b1 = ((const float4*)bias)[1];
        o0.x += b0.x; o0.y += b0.y; o0.z += b0.z; o0.w += b0.w;
        o1.x += b1.x; o1.y += b1.y; o1.z += b1.z; o1.w += b1.w;
    }
    if (relu) {
        o0.x = fmaxf(o0.x, 0.f); o0.y = fmaxf(o0.y, 0.f);
        o0.z = fmaxf(o0.z, 0.f); o0.w = fmaxf(o0.w, 0.f);
        o1.x = fmaxf(o1.x, 0.f); o1.y = fmaxf(o1.y, 0.f);
        o1.z = fmaxf(o1.z, 0.f); o1.w = fmaxf(o1.w, 0.f);
    }
    ((float4*)out)[(size_t)node * 2]     = o0;
    ((float4*)out)[(size_t)node * 2 + 1] = o1;
}

// width-2 gather: thread per node
__global__ void k_agg2(const float* __restrict__ u, const EdgeRec* __restrict__ edges,
                       const int* __restrict__ rowoff, const int* __restrict__ rowend,
                       const float* __restrict__ dis,
                       const float* __restrict__ bias,
                       float* __restrict__ out, int N) {
    int node = blockIdx.x * blockDim.x + threadIdx.x;
    if (node >= N) return;
    float a0 = 0.f, a1 = 0.f, b0 = 0.f, b1 = 0.f;
    int e = rowoff[node], e1 = rowend[node];
    const float2* U2 = (const float2*)u;
    for (; e + 2 <= e1; e += 2) {
        u64 er0 = *(const u64*)(edges + e);
        u64 er1 = *(const u64*)(edges + e + 1);
        int s0 = (int)(u32)er0; float w0 = __uint_as_float((u32)(er0 >> 32));
        int s1 = (int)(u32)er1; float w1 = __uint_as_float((u32)(er1 >> 32));
        float2 q0 = U2[s0];
        float2 q1 = U2[s1];
        a0 = fmaf(w0, q0.x, a0); a1 = fmaf(w0, q0.y, a1);
        b0 = fmaf(w1, q1.x, b0); b1 = fmaf(w1, q1.y, b1);
    }
    for (; e < e1; e++) {
        u64 er = *(const u64*)(edges + e);
        int s = (int)(u32)er; float wv = __uint_as_float((u32)(er >> 32));
        float2 q = U2[s];
        a0 = fmaf(wv, q.x, a0); a1 = fmaf(wv, q.y, a1);
    }
    {
        float dv = dis[node];
        float sw = dv * dv;
        float2 q = U2[node];
        b0 = fmaf(sw, q.x, b0); b1 = fmaf(sw, q.y, b1);
    }
    float2 o;
    o.x = a0 + b0 + bias[0];
    o.y = a1 + b1 + bias[1];
    ((float2*)out)[node] = o;
}

// head mm 64->32: register-blocked FFMA2, tile 96 rows x 32 cols, 96 threads
__global__ void __launch_bounds__(96) k_mmh1(const float* __restrict__ A,
                                             const float* __restrict__ W,
                                             float* __restrict__ C, int N) {
    __shared__ float As[96][65];
    __shared__ float Ws[64][32];
    int tid = threadIdx.x;
    int row0 = blockIdx.x * 96;
    {
        const float4* Wv = (const float4*)W;
        float4* Wsv = (float4*)&Ws[0][0];
        for (int i = tid; i < 512; i += 96) Wsv[i] = Wv[i];
    }
    for (int i = tid; i < 96 * 16; i += 96) {
        int r = i >> 4, kq = i & 15;
        int row = row0 + r;
        float4 v = make_float4(0.f, 0.f, 0.f, 0.f);
        if (row < N) v = ((const float4*)A)[(size_t)row * 16 + kq];
        As[r][kq * 4 + 0] = v.x;
        As[r][kq * 4 + 1] = v.y;
        As[r][kq * 4 + 2] = v.z;
        As[r][kq * 4 + 3] = v.w;
    }
    __syncthreads();

    int tx = tid & 3, ty = tid >> 2;
    u64 acc2[4][4];
#pragma unroll
    for (int i = 0; i < 4; i++)
#pragma unroll
        for (int j = 0; j < 4; j++) acc2[i][j] = 0ull;

#pragma unroll 8
    for (int k = 0; k < 64; k++) {
        u64 ad[4];
#pragma unroll
        for (int i = 0; i < 4; i++) {
            float a = As[ty * 4 + i][k];
            ad[i] = pack2(a, a);
        }
        const u64* wp = (const u64*)&Ws[k][tx * 8];
        u64 w0 = wp[0], w1 = wp[1], w2 = wp[2], w3 = wp[3];
#pragma unroll
        for (int i = 0; i < 4; i++) {
            ffma2(acc2[i][0], ad[i], w0);
            ffma2(acc2[i][1], ad[i], w1);
            ffma2(acc2[i][2], ad[i], w2);
            ffma2(acc2[i][3], ad[i], w3);
        }
    }
#pragma unroll
    for (int i = 0; i < 4; i++) {
        int row = row0 + ty * 4 + i;
        if (row >= N) continue;
        float c[8];
#pragma unroll
        for (int j = 0; j < 4; j++) unpack2(acc2[i][j], c[2 * j], c[2 * j + 1]);
        ((float4*)C)[(size_t)row * 8 + tx * 2 + 0] = make_float4(c[0], c[1], c[2], c[3]);
        ((float4*)C)[(size_t)row * 8 + tx * 2 + 1] = make_float4(c[4], c[5], c[6], c[7]);
    }
}

// head mm 32->8: warp per node; lane = (k-chunk c)*8 + col j; shfl reduce
__global__ void k_mm32x8(const float* __restrict__ A, const float* __restrict__ W,
                         float* __restrict__ C, int N) {
    __shared__ float Ws[32 * 8];
    int tid = threadIdx.x;
    for (int i = tid; i < 256; i += blockDim.x) Ws[i] = W[i];
    __syncthreads();
    int node = blockIdx.x * 8 + (tid >> 5);
    int lane = tid & 31;
    if (node >= N) return;
    int j = lane & 7, c = lane >> 3;
    const float4* ap = (const float4*)(A + (size_t)node * 32 + c * 8);
    float4 q0 = ap[0], q1 = ap[1];
    float av[8] = {q0.x, q0.y, q0.z, q0.w, q1.x, q1.y, q1.z, q1.w};
    float acc = 0.f;
#pragma unroll
    for (int kk = 0; kk < 8; kk++)
        acc = fmaf(av[kk], Ws[(c * 8 + kk) * 8 + j], acc);
    acc += __shfl_xor_sync(0xffffffffu, acc, 8);
    acc += __shfl_xor_sync(0xffffffffu, acc, 16);
    if (lane < 8) C[(size_t)node * 8 + j] = acc;
}

// head mm 8->2: thread per node
__global__ void k_mm8x2(const float* __restrict__ A, const float* __restrict__ W,
                        float* __restrict__ C, int N) {
    int node = blockIdx.x * blockDim.x + threadIdx.x;
    if (node >= N) return;
    const float4* ap = (const float4*)(A + (size_t)node * 8);
    float4 q0 = ap[0], q1 = ap[1];
    float av[8] = {q0.x, q0.y, q0.z, q0.w, q1.x, q1.y, q1.z, q1.w};
    float c0 = 0.f, c1 = 0.f;
#pragma unroll
    for (int kk = 0; kk < 8; kk++) {
        float w0 = __ldg(W + kk * 2);
        float w1 = __ldg(W + kk * 2 + 1);
        c0 = fmaf(av[kk], w0, c0);
        c1 = fmaf(av[kk], w1, c1);
    }
    ((float2*)C)[node] = make_float2(c0, c1);
}

// =============== tensor-core matmul (main loop) ===============
template <int RECALL>
__global__ void __launch_bounds__(256) k_mmTC(
    const __half* __restrict__ A16, const __half* __restrict__ W16,
    const float* __restrict__ Wx, const float* __restrict__ brv,
    const float* __restrict__ aggx,
    float* __restrict__ out32, __half* __restrict__ out16, int N) {
    __shared__ __align__(32) __half Ws[64 * 64];
    __shared__ __align__(32) float stage[128 * 64];
    int tid = threadIdx.x;
    int warp = tid >> 5;
    int row0 = blockIdx.x * 128;

    {
        const uint4* src = (const uint4*)W16;
        uint4* dst = (uint4*)Ws;
        for (int i = tid; i < 512; i += 256) dst[i] = src[i];
    }
    __syncthreads();

    wmma::fragment<wmma::accumulator, 16, 16, 16, float> acc[4];
#pragma unroll
    for (int nt = 0; nt < 4; nt++) wmma::fill_fragment(acc[nt], 0.f);

    const __half* Abase = A16 + (size_t)(row0 + warp * 16) * 64;
#pragma unroll
    for (int kt = 0; kt < 4; kt++) {
        wmma::fragment<wmma::matrix_a, 16, 16, 16, __half, wmma::row_major> af;
        wmma::load_matrix_sync(af, Abase + kt * 16, 64);
#pragma unroll
        for (int nt = 0; nt < 4; nt++) {
            wmma::fragment<wmma::matrix_b, 16, 16, 16, __half, wmma::row_major> bf;
            wmma::load_matrix_sync(bf, Ws + kt * 16 * 64 + nt * 16, 64);
            wmma::mma_sync(acc[nt], af, bf, acc[nt]);
        }
    }
#pragma unroll
    for (int nt = 0; nt < 4; nt++)
        wmma::store_matrix_sync(stage + warp * 16 * 64 + nt * 16, acc[nt], 64,
                                wmma::mem_row_major);
    __syncthreads();

    for (int i = tid; i < 128 * 16; i += 256) {
        int row = i >> 4;
        int q = i & 15;
        int grow = row0 + row;
        if (grow >= N) break;
        float4 c = ((const float4*)stage)[i];
        if (RECALL) {
            float a0 = aggx[grow * 3], a1 = aggx[grow * 3 + 1], a2 = aggx[grow * 3 + 2];
            int col = q * 4;
#pragma unroll
            for (int jj = 0; jj < 4; jj++) {
                float add = fmaf(a0, Wx[col + jj],
                             fmaf(a1, Wx[64 + col + jj],
                              fmaf(a2, Wx[128 + col + jj], brv[col + jj])));
                (&c.x)[jj] += add;
            }
            ((float4*)out32)[(size_t)grow * 16 + q] = c;
        }
        uint2 m;
        m.x = f2h(c.x, c.y);
        m.y = f2h(c.z, c.w);
        ((uint2*)out16)[(size_t)grow * 16 + q] = m;
    }
}

// =============== host launch ===============

extern "C" void kernel_launch(void* const* d_in, const int* in_sizes, int n_in,
                              void* d_out, int out_size) {
    const float* x   = (const float*)d_in[0];
    const float* Wp  = (const float*)d_in[1];
    const float* bp  = (const float*)d_in[2];
    const float* Wr  = (const float*)d_in[3];
    const float* br  = (const float*)d_in[4];
    const float* W11 = (const float*)d_in[5];
    const float* b11 = (const float*)d_in[6];
    const float* W12 = (const float*)d_in[7];
    const float* b12 = (const float*)d_in[8];
    const float* W21 = (const float*)d_in[9];
    const float* b21 = (const float*)d_in[10];
    const float* W22 = (const float*)d_in[11];
    const float* b22 = (const float*)d_in[12];
    const float* Wh1 = (const float*)d_in[13];
    const float* bh1 = (const float*)d_in[14];
    const float* Wh2 = (const float*)d_in[15];
    const float* bh2 = (const float*)d_in[16];
    const float* Wh3 = (const float*)d_in[17];
    const float* bh3 = (const float*)d_in[18];
    const int*   ei  = (const int*)d_in[19];

    int N = in_sizes[0] / 3;
    int E = in_sizes[19] / 2;
    const int* esrc = ei;
    const int* edst = ei + E;

    int *zero, *rowoff, *rowend;
    float *dis, *aggx;
    EdgeRec* edges;
    float4 *t4, *u4, *v4;
    uint4 *t16p, *u16p, *v16p, *w16p;
    cudaGetSymbolAddress((void**)&zero, g_zero);
    cudaGetSymbolAddress((void**)&rowoff, g_rowoff);
    cudaGetSymbolAddress((void**)&rowend, g_rowend);
    cudaGetSymbolAddress((void**)&dis, g_dis);
    cudaGetSymbolAddress((void**)&edges, g_edges);
    cudaGetSymbolAddress((void**)&aggx, g_aggx);
    cudaGetSymbolAddress((void**)&t4, g_t);
    cudaGetSymbolAddress((void**)&u4, g_u);
    cudaGetSymbolAddress((void**)&v4, g_v);
    cudaGetSymbolAddress((void**)&t16p, g_t16);
    cudaGetSymbolAddress((void**)&u16p, g_u16);
    cudaGetSymbolAddress((void**)&v16p, g_v16);
    cudaGetSymbolAddress((void**)&w16p, g_w16);
    int* counts = zero;
    int* cursor = zero + NCAP;
    int* total  = zero + 2 * NCAP;
    float* t = (float*)t4;
    float* u = (float*)u4;
    float* v = (float*)v4;
    __half* t16 = (__half*)t16p;
    __half* u16 = (__half*)u16p;
    __half* v16 = (__half*)v16p;
    __half* w16 = (__half*)w16p;
    __half* Wr16   = w16;
    __half* W11_16 = w16 + 4096;
    __half* W12_16 = w16 + 2 * 4096;
    __half* W21_16 = w16 + 3 * 4096;
    __half* W22_16 = w16 + 4 * 4096;

    int nbE = (E + 255) / 256;
    int nbN = (N + 255) / 256;
    int nbWarp = (N + 7) / 8;       // 8 nodes per 256-thread block
    int nbAgg = (N + 15) / 16;      // agg: 16 nodes per 256-thread block
    int nbTC = (N + 127) / 128;     // tensor-core mm tiles
    int nbMMH = (N + 95) / 96;      // head mm1 tiles

    // ---- graph setup (5 launches) ----
    cudaMemsetAsync(zero, 0, (size_t)(2 * NCAP + 4) * sizeof(int), 0);
    k_count<<<nbE, 256>>>(edst, E, counts);
    k_setup2<<<nbN, 256>>>(counts, dis, rowoff, rowend, total, N,
                           Wr, W11, W12, W21, W22, w16);
    k_fill<<<nbE, 256>>>(esrc, edst, E, rowoff, cursor, dis, edges);
    k_aggx_proj<<<nbWarp, 256>>>(x, edges, rowoff, rowend, dis,
                                 Wp, bp, aggx, t, t16, N);

    const float* Wrx = Wr + 64 * 64;  // rows 64..66 of Wr (x part)

    // ---- iterations ----
    for (int it = 0; it < ITERS; it++) {
        k_aggv<0, 0, 0><<<nbAgg, 256>>>(t16p, edges, rowoff, rowend, dis,
                                        nullptr, nullptr, nullptr, v16p, N);
        k_mmTC<1><<<nbTC, 256>>>(v16, Wr16, Wrx, br, aggx, t, t16, N);
        // block 1
        k_mmTC<0><<<nbTC, 256>>>(t16, W11_16, nullptr, nullptr, nullptr,
                                 nullptr, u16, N);
        k_aggv<1, 0, 0><<<nbAgg, 256>>>(u16p, edges, rowoff, rowend, dis,
                                        b11, nullptr, nullptr, v16p, N);
        k_mmTC<0><<<nbTC, 256>>>(v16, W12_16, nullptr, nullptr, nullptr,
                                 nullptr, u16, N);
        k_aggv<1, 1, 1><<<nbAgg, 256>>>(u16p, edges, rowoff, rowend, dis,
                                        b12, t, t, t16p, N);
        // block 2
        k_mmTC<0><<<nbTC, 256>>>(t16, W21_16, nullptr, nullptr, nullptr,
                                 nullptr, u16, N);
        k_aggv<1, 0, 0><<<nbAgg, 256>>>(u16p, edges, rowoff, rowend, dis,
                                        b21, nullptr, nullptr, v16p, N);
        k_mmTC<0><<<nbTC, 256>>>(v16, W22_16, nullptr, nullptr, nullptr,
                                 nullptr, u16, N);
        k_aggv<1, 1, 1><<<nbAgg, 256>>>(u16p, edges, rowoff, rowend, dis,
                                        b22, t, t, t16p, N);
    }

    // ---- head (fp32, optimized kernels) ----
    k_mmh1<<<nbMMH, 96>>>(t, Wh1, u, N);
    k_agg32<<<nbWarp, 256>>>(u, edges, rowoff, rowend, dis, bh1, 1, v, N);
    k_mm32x8<<<nbWarp, 256>>>(v, Wh2, u, N);
    k_agg8<<<nbN, 256>>>(u, edges, rowoff, rowend, dis, bh2, 1, v, N);
    k_mm8x2<<<nbN, 256>>>(v, Wh3, u, N);
    k_agg2<<<nbN, 256>>>(u, edges, rowoff, rowend, dis, bh3, (float*)d_out, N);
}

// round 16
// speedup vs baseline: 1.1242x; 1.1242x over previous
#include <cuda_runtime.h>
#include <cuda_fp16.h>
#include <mma.h>
#include <math.h>

using namespace nvcuda;

// Problem-fixed capacities (dataset constants)
#define NCAP 100000
#define NPAD (NCAP + 128)
#define ECAP 1600000
#define ITERS 5

struct __align__(8) EdgeRec { int src; float w; };
typedef unsigned long long u64;
typedef unsigned int u32;

// ---- static device scratch (no allocation allowed) ----
// zero region: [counts | cursor | total]
__device__ int     g_zero[2 * NCAP + 4];
__device__ int     g_rowoff[NCAP];
__device__ int     g_rowend[NCAP];
__device__ float   g_dis[NCAP];
__device__ EdgeRec g_edges[ECAP];
__device__ float   g_aggx[NCAP * 3];
__device__ float4  g_t[NCAP * 16];
__device__ float4  g_u[NCAP * 16];
__device__ float4  g_v[NCAP * 16];
// fp16 mirrors, padded (64 halfs = 16 uint2 per node)
__device__ uint4   g_t16[NPAD * 8];
__device__ uint4   g_u16[NPAD * 8];
__device__ uint4   g_v16[NPAD * 8];
// fp16 weights: Wr_t, W11, W12, W21, W22 (each 64x64)
__device__ uint4   g_w16[5 * 4096 / 8];

// ---- packed fp32x2 helpers ----
__device__ __forceinline__ u64 pack2(float x, float y) {
    u64 r; asm("mov.b64 %0, {%1, %2};" : "=l"(r) : "f"(x), "f"(y)); return r;
}
__device__ __forceinline__ void unpack2(u64 v, float& x, float& y) {
    asm("mov.b64 {%0, %1}, %2;" : "=f"(x), "=f"(y) : "l"(v));
}
__device__ __forceinline__ void ffma2(u64& d, u64 a, u64 b) {
    asm("fma.rn.f32x2 %0, %1, %2, %0;" : "+l"(d) : "l"(a), "l"(b));
}

// ---- fp16 pack/unpack ----
__device__ __forceinline__ float2 h2f(u32 q) {
    __half2 h = *reinterpret_cast<__half2*>(&q);
    return __half22float2(h);
}
__device__ __forceinline__ u32 f2h(float x, float y) {
    __half2 h = __floats2half2_rn(x, y);
    return *reinterpret_cast<u32*>(&h);
}

// =============== graph setup kernels ===============

__global__ void k_count(const int* __restrict__ dst, int E, int* __restrict__ counts) {
    int i = blockIdx.x * blockDim.x + threadIdx.x;
    if (i < E) atomicAdd(&counts[dst[i]], 1);
}

__global__ void k_setup2(const int* __restrict__ counts, float* __restrict__ dis,
                         int* __restrict__ rowoff, int* __restrict__ rowend,
                         int* __restrict__ total, int N,
                         const float* __restrict__ Wr, const float* __restrict__ W11,
                         const float* __restrict__ W12, const float* __restrict__ W21,
                         const float* __restrict__ W22, __half* __restrict__ w16) {
    int i = blockIdx.x * blockDim.x + threadIdx.x;
    if (i < 4096) {
        w16[i]            = __float2half_rn(Wr[i]);
        w16[4096 + i]     = __float2half_rn(W11[i]);
        w16[2 * 4096 + i] = __float2half_rn(W12[i]);
        w16[3 * 4096 + i] = __float2half_rn(W21[i]);
        w16[4 * 4096 + i] = __float2half_rn(W22[i]);
    }
    if (i < N) {
        int c = counts[i];
        dis[i] = rsqrtf((float)(c + 1));
        int off = atomicAdd(total, c);
        rowoff[i] = off;
        rowend[i] = off + c;
    }
}

__global__ void k_fill(const int* __restrict__ srcA, const int* __restrict__ dstA, int E,
                       const int* __restrict__ rowoff, int* __restrict__ cursor,
                       const float* __restrict__ dis, EdgeRec* __restrict__ edges) {
    int i = blockIdx.x * blockDim.x + threadIdx.x;
    if (i >= E) return;
    int s = srcA[i], d = dstA[i];
    int pos = rowoff[d] + atomicAdd(&cursor[d], 1);
    EdgeRec r;
    r.src = s;
    r.w = dis[s] * dis[d];
    edges[pos] = r;
}

// fused: aggx = agg(x) + projection
__global__ void k_aggx_proj(const float* __restrict__ x, const EdgeRec* __restrict__ edges,
                            const int* __restrict__ rowoff, const int* __restrict__ rowend,
                            const float* __restrict__ dis,
                            const float* __restrict__ Wp, const float* __restrict__ bp,
                            float* __restrict__ aggx, float* __restrict__ t,
                            __half* __restrict__ t16, int N) {
    int node = blockIdx.x * 8 + (threadIdx.x >> 5);
    int lane = threadIdx.x & 31;
    if (node >= N) return;
    float a0 = 0.f, a1 = 0.f, a2 = 0.f;
    int e0 = rowoff[node], e1 = rowend[node];
    for (int e = e0 + lane; e < e1; e += 32) {
        EdgeRec r = edges[e];
        const float* xp = x + (size_t)r.src * 3;
        a0 = fmaf(r.w, __ldg(xp), a0);
        a1 = fmaf(r.w, __ldg(xp + 1), a1);
        a2 = fmaf(r.w, __ldg(xp + 2), a2);
    }
    if (lane == 0) {
        float dv = dis[node];
        float sw = dv * dv;
        const float* xp = x + (size_t)node * 3;
        a0 = fmaf(sw, xp[0], a0);
        a1 = fmaf(sw, xp[1], a1);
        a2 = fmaf(sw, xp[2], a2);
    }
#pragma unroll
    for (int off = 16; off > 0; off >>= 1) {
        a0 += __shfl_xor_sync(0xffffffffu, a0, off);
        a1 += __shfl_xor_sync(0xffffffffu, a1, off);
        a2 += __shfl_xor_sync(0xffffffffu, a2, off);
    }
    if (lane == 0) {
        aggx[node * 3] = a0;
        aggx[node * 3 + 1] = a1;
        aggx[node * 3 + 2] = a2;
    }
#pragma unroll
    for (int jj = 0; jj < 2; jj++) {
        int j = 2 * lane + jj;
        float acc = bp[j];
        acc = fmaf(a0, Wp[j], acc);
        acc = fmaf(a1, Wp[64 + j], acc);
        acc = fmaf(a2, Wp[128 + j], acc);
        acc = fmaxf(acc, 0.f);
        t[(size_t)node * 64 + j] = acc;
        t16[(size_t)node * 64 + j] = __float2half_rn(acc);
    }
}

// =============== main aggregation: half-warp gather, 8-deep unroll ===============
template <int RELU, int RES, int W32>
__global__ void __launch_bounds__(256) k_aggv(
    const uint2* __restrict__ U16, const EdgeRec* __restrict__ edges,
    const int* __restrict__ rowoff, const int* __restrict__ rowend,
    const float* __restrict__ dis,
    const float* __restrict__ bias, const float* __restrict__ res,
    float* __restrict__ out, uint2* __restrict__ out16, int N) {
    int tid = threadIdx.x;
    int warp = tid >> 5;
    int half = (tid >> 4) & 1;
    int sub = tid & 15;
    int node = blockIdx.x * 16 + warp * 2 + half;
    if (node >= N) return;

    float ac0[4] = {0.f, 0.f, 0.f, 0.f};
    float ac1[4] = {0.f, 0.f, 0.f, 0.f};
    float ac2[4] = {0.f, 0.f, 0.f, 0.f};
    float ac3[4] = {0.f, 0.f, 0.f, 0.f};

    int e = rowoff[node];
    int e1 = rowend[node];
    for (; e + 8 <= e1; e += 8) {
        u64 er0 = *(const u64*)(edges + e);
        u64 er1 = *(const u64*)(edges + e + 1);
        u64 er2 = *(const u64*)(edges + e + 2);
        u64 er3 = *(const u64*)(edges + e + 3);
        u64 er4 = *(const u64*)(edges + e + 4);
        u64 er5 = *(const u64*)(edges + e + 5);
        u64 er6 = *(const u64*)(edges + e + 6);
        u64 er7 = *(const u64*)(edges + e + 7);
        int s0 = (int)(u32)er0; float w0 = __uint_as_float((u32)(er0 >> 32));
        int s1 = (int)(u32)er1; float w1 = __uint_as_float((u32)(er1 >> 32));
        int s2 = (int)(u32)er2; float w2 = __uint_as_float((u32)(er2 >> 32));
        int s3 = (int)(u32)er3; float w3 = __uint_as_float((u32)(er3 >> 32));
        int s4 = (int)(u32)er4; float w4 = __uint_as_float((u32)(er4 >> 32));
        int s5 = (int)(u32)er5; float w5 = __uint_as_float((u32)(er5 >> 32));
        int s6 = (int)(u32)er6; float w6 = __uint_as_float((u32)(er6 >> 32));
        int s7 = (int)(u32)er7; float w7 = __uint_as_float((u32)(er7 >> 32));
        uint2 q0 = U16[(size_t)s0 * 16 + sub];
        uint2 q1 = U16[(size_t)s1 * 16 + sub];
        uint2 q2 = U16[(size_t)s2 * 16 + sub];
        uint2 q3 = U16[(size_t)s3 * 16 + sub];
        uint2 q4 = U16[(size_t)s4 * 16 + sub];
        uint2 q5 = U16[(size_t)s5 * 16 + sub];
        uint2 q6 = U16[(size_t)s6 * 16 + sub];
        uint2 q7 = U16[(size_t)s7 * 16 + sub];
        {
            float2 fa = h2f(q0.x), fb = h2f(q0.y);
            ac0[0] = fmaf(w0, fa.x, ac0[0]); ac0[1] = fmaf(w0, fa.y, ac0[1]);
            ac0[2] = fmaf(w0, fb.x, ac0[2]); ac0[3] = fmaf(w0, fb.y, ac0[3]);
        }
        {
            float2 fa = h2f(q1.x), fb = h2f(q1.y);
            ac1[0] = fmaf(w1, fa.x, ac1[0]); ac1[1] = fmaf(w1, fa.y, ac1[1]);
            ac1[2] = fmaf(w1, fb.x, ac1[2]); ac1[3] = fmaf(w1, fb.y, ac1[3]);
        }
        {
            float2 fa = h2f(q2.x), fb = h2f(q2.y);
            ac2[0] = fmaf(w2, fa.x, ac2[0]); ac2[1] = fmaf(w2, fa.y, ac2[1]);
            ac2[2] = fmaf(w2, fb.x, ac2[2]); ac2[3] = fmaf(w2, fb.y, ac2[3]);
        }
        {
            float2 fa = h2f(q3.x), fb = h2f(q3.y);
            ac3[0] = fmaf(w3, fa.x, ac3[0]); ac3[1] = fmaf(w3, fa.y, ac3[1]);
            ac3[2] = fmaf(w3, fb.x, ac3[2]); ac3[3] = fmaf(w3, fb.y, ac3[3]);
        }
        {
            float2 fa = h2f(q4.x), fb = h2f(q4.y);
            ac0[0] = fmaf(w4, fa.x, ac0[0]); ac0[1] = fmaf(w4, fa.y, ac0[1]);
            ac0[2] = fmaf(w4, fb.x, ac0[2]); ac0[3] = fmaf(w4, fb.y, ac0[3]);
        }
        {
            float2 fa = h2f(q5.x), fb = h2f(q5.y);
            ac1[0] = fmaf(w5, fa.x, ac1[0]); ac1[1] = fmaf(w5, fa.y, ac1[1]);
            ac1[2] = fmaf(w5, fb.x, ac1[2]); ac1[3] = fmaf(w5, fb.y, ac1[3]);
        }
        {
            float2 fa = h2f(q6.x), fb = h2f(q6.y);
            ac2[0] = fmaf(w6, fa.x, ac2[0]); ac2[1] = fmaf(w6, fa.y, ac2[1]);
            ac2[2] = fmaf(w6, fb.x, ac2[2]); ac2[3] = fmaf(w6, fb.y, ac2[3]);
        }
        {
            float2 fa = h2f(q7.x), fb = h2f(q7.y);
            ac3[0] = fmaf(w7, fa.x, ac3[0]); ac3[1] = fmaf(w7, fa.y, ac3[1]);
            ac3[2] = fmaf(w7, fb.x, ac3[2]); ac3[3] = fmaf(w7, fb.y, ac3[3]);
        }
    }
    for (; e + 4 <= e1; e += 4) {
        u64 er0 = *(const u64*)(edges + e);
        u64 er1 = *(const u64*)(edges + e + 1);
        u64 er2 = *(const u64*)(edges + e + 2);
        u64 er3 = *(const u64*)(edges + e + 3);
        int s0 = (int)(u32)er0; float w0 = __uint_as_float((u32)(er0 >> 32));
        int s1 = (int)(u32)er1; float w1 = __uint_as_float((u32)(er1 >> 32));
        int s2 = (int)(u32)er2; float w2 = __uint_as_float((u32)(er2 >> 32));
        int s3 = (int)(u32)er3; float w3 = __uint_as_float((u32)(er3 >> 32));
        uint2 q0 = U16[(size_t)s0 * 16 + sub];
        uint2 q1 = U16[(size_t)s1 * 16 + sub];
        uint2 q2 = U16[(size_t)s2 * 16 + sub];
        uint2 q3 = U16[(size_t)s3 * 16 + sub];
        float2 f0a = h2f(q0.x), f0b = h2f(q0.y);
        float2 f1a = h2f(q1.x), f1b = h2f(q1.y);
        float2 f2a = h2f(q2.x), f2b = h2f(q2.y);
        float2 f3a = h2f(q3.x), f3b = h2f(q3.y);
        ac0[0] = fmaf(w0, f0a.x, ac0[0]); ac0[1] = fmaf(w0, f0a.y, ac0[1]);
        ac0[2] = fmaf(w0, f0b.x, ac0[2]); ac0[3] = fmaf(w0, f0b.y, ac0[3]);
        ac1[0] = fmaf(w1, f1a.x, ac1[0]); ac1[1] = fmaf(w1, f1a.y, ac1[1]);
        ac1[2] = fmaf(w1, f1b.x, ac1[2]); ac1[3] = fmaf(w1, f1b.y, ac1[3]);
        ac2[0] = fmaf(w2, f2a.x, ac2[0]); ac2[1] = fmaf(w2, f2a.y, ac2[1]);
        ac2[2] = fmaf(w2, f2b.x, ac2[2]); ac2[3] = fmaf(w2, f2b.y, ac2[3]);
        ac3[0] = fmaf(w3, f3a.x, ac3[0]); ac3[1] = fmaf(w3, f3a.y, ac3[1]);
        ac3[2] = fmaf(w3, f3b.x, ac3[2]); ac3[3] = fmaf(w3, f3b.y, ac3[3]);
    }
    for (; e < e1; e++) {
        u64 er = *(const u64*)(edges + e);
        int s = (int)(u32)er; float wv = __uint_as_float((u32)(er >> 32));
        uint2 q = U16[(size_t)s * 16 + sub];
        float2 fa = h2f(q.x), fb = h2f(q.y);
        ac0[0] = fmaf(wv, fa.x, ac0[0]); ac0[1] = fmaf(wv, fa.y, ac0[1]);
        ac0[2] = fmaf(wv, fb.x, ac0[2]); ac0[3] = fmaf(wv, fb.y, ac0[3]);
    }
    // self loop
    {
        float dv = dis[node];
        float sw = dv * dv;
        uint2 q = U16[(size_t)node * 16 + sub];
        float2 fa = h2f(q.x), fb = h2f(q.y);
        ac1[0] = fmaf(sw, fa.x, ac1[0]); ac1[1] = fmaf(sw, fa.y, ac1[1]);
        ac1[2] = fmaf(sw, fb.x, ac1[2]); ac1[3] = fmaf(sw, fb.y, ac1[3]);
    }
    float4 o;
    o.x = (ac0[0] + ac1[0]) + (ac2[0] + ac3[0]);
    o.y = (ac0[1] + ac1[1]) + (ac2[1] + ac3[1]);
    o.z = (ac0[2] + ac1[2]) + (ac2[2] + ac3[2]);
    o.w = (ac0[3] + ac1[3]) + (ac2[3] + ac3[3]);
    if (bias) {
        float4 b = ((const float4*)bias)[sub];
        o.x += b.x; o.y += b.y; o.z += b.z; o.w += b.w;
    }
    if (RES) {
        float4 rr = ((const float4*)res)[(size_t)node * 16 + sub];
        o.x += rr.x; o.y += rr.y; o.z += rr.z; o.w += rr.w;
    }
    if (RELU) {
        o.x = fmaxf(o.x, 0.f); o.y = fmaxf(o.y, 0.f);
        o.z = fmaxf(o.z, 0.f); o.w = fmaxf(o.w, 0.f);
    }
    if (W32) ((float4*)out)[(size_t)node * 16 + sub] = o;
    {
        uint2 m;
        m.x = f2h(o.x, o.y);
        m.y = f2h(o.z, o.w);
        out16[(size_t)node * 16 + sub] = m;
    }
}

// =============== head kernels (fp32, optimized) ===============

// width-32 gather: warp per node, 4-deep unroll
__global__ void k_agg32(const float* __restrict__ u, const EdgeRec* __restrict__ edges,
                        const int* __restrict__ rowoff, const int* __restrict__ rowend,
                        const float* __restrict__ dis,
                        const float* __restrict__ bias, int relu,
                        float* __restrict__ out, int N) {
    int node = blockIdx.x * 8 + (threadIdx.x >> 5);
    int lane = threadIdx.x & 31;
    if (node >= N) return;
    float a0 = 0.f, a1 = 0.f, a2 = 0.f, a3 = 0.f;
    int e = rowoff[node], e1 = rowend[node];
    for (; e + 4 <= e1; e += 4) {
        u64 er0 = *(const u64*)(edges + e);
        u64 er1 = *(const u64*)(edges + e + 1);
        u64 er2 = *(const u64*)(edges + e + 2);
        u64 er3 = *(const u64*)(edges + e + 3);
        int s0 = (int)(u32)er0; float w0 = __uint_as_float((u32)(er0 >> 32));
        int s1 = (int)(u32)er1; float w1 = __uint_as_float((u32)(er1 >> 32));
        int s2 = (int)(u32)er2; float w2 = __uint_as_float((u32)(er2 >> 32));
        int s3 = (int)(u32)er3; float w3 = __uint_as_float((u32)(er3 >> 32));
        float f0 = u[(size_t)s0 * 32 + lane];
        float f1 = u[(size_t)s1 * 32 + lane];
        float f2 = u[(size_t)s2 * 32 + lane];
        float f3 = u[(size_t)s3 * 32 + lane];
        a0 = fmaf(w0, f0, a0);
        a1 = fmaf(w1, f1, a1);
        a2 = fmaf(w2, f2, a2);
        a3 = fmaf(w3, f3, a3);
    }
    for (; e < e1; e++) {
        u64 er = *(const u64*)(edges + e);
        int s = (int)(u32)er; float wv = __uint_as_float((u32)(er >> 32));
        a0 = fmaf(wv, u[(size_t)s * 32 + lane], a0);
    }
    float dv = dis[node];
    a1 = fmaf(dv * dv, u[(size_t)node * 32 + lane], a1);
    float acc = (a0 + a1) + (a2 + a3);
    if (bias) acc += bias[lane];
    if (relu) acc = fmaxf(acc, 0.f);
    out[(size_t)node * 32 + lane] = acc;
}

// width-8 gather: thread per node, float4 loads, 2-edge unroll
__global__ void k_agg8(const float* __restrict__ u, const EdgeRec* __restrict__ edges,
                       const int* __restrict__ rowoff, const int* __restrict__ rowend,
                       const float* __restrict__ dis,
                       const float* __restrict__ bias, int relu,
                       float* __restrict__ out, int N) {
    int node = blockIdx.x * blockDim.x + threadIdx.x;
    if (node >= N) return;
    float aA[8] = {0.f, 0.f, 0.f, 0.f, 0.f, 0.f, 0.f, 0.f};
    float aB[8] = {0.f, 0.f, 0.f, 0.f, 0.f, 0.f, 0.f, 0.f};
    int e = rowoff[node], e1 = rowend[node];
    const float4* U4 = (const float4*)u;
    for (; e + 2 <= e1; e += 2) {
        u64 er0 = *(const u64*)(edges + e);
        u64 er1 = *(const u64*)(edges + e + 1);
        int s0 = (int)(u32)er0; float w0 = __uint_as_float((u32)(er0 >> 32));
        int s1 = (int)(u32)er1; float w1 = __uint_as_float((u32)(er1 >> 32));
        float4 x0 = U4[(size_t)s0 * 2],     y0 = U4[(size_t)s0 * 2 + 1];
        float4 x1 = U4[(size_t)s1 * 2],     y1 = U4[(size_t)s1 * 2 + 1];
        aA[0] = fmaf(w0, x0.x, aA[0]); aA[1] = fmaf(w0, x0.y, aA[1]);
        aA[2] = fmaf(w0, x0.z, aA[2]); aA[3] = fmaf(w0, x0.w, aA[3]);
        aA[4] = fmaf(w0, y0.x, aA[4]); aA[5] = fmaf(w0, y0.y, aA[5]);
        aA[6] = fmaf(w0, y0.z, aA[6]); aA[7] = fmaf(w0, y0.w, aA[7]);
        aB[0] = fmaf(w1, x1.x, aB[0]); aB[1] = fmaf(w1, x1.y, aB[1]);
        aB[2] = fmaf(w1, x1.z, aB[2]); aB[3] = fmaf(w1, x1.w, aB[3]);
        aB[4] = fmaf(w1, y1.x, aB[4]); aB[5] = fmaf(w1, y1.y, aB[5]);
        aB[6] = fmaf(w1, y1.z, aB[6]); aB[7] = fmaf(w1, y1.w, aB[7]);
    }
    for (; e < e1; e++) {
        u64 er = *(const u64*)(edges + e);
        int s = (int)(u32)er; float wv = __uint_as_float((u32)(er >> 32));
        float4 x0 = U4[(size_t)s * 2], y0 = U4[(size_t)s * 2 + 1];
        aA[0] = fmaf(wv, x0.x, aA[0]); aA[1] = fmaf(wv, x0.y, aA[1]);
        aA[2] = fmaf(wv, x0.z, aA[2]); aA[3] = fmaf(wv, x0.w, aA[3]);
        aA[4] = fmaf(wv, y0.x, aA[4]); aA[5] = fmaf(wv, y0.y, aA[5]);
        aA[6] = fmaf(wv, y0.z, aA[6]); aA[7] = fmaf(wv, y0.w, aA[7]);
    }
    {
        float dv = dis[node];
        float sw = dv * dv;
        float4 x0 = U4[(size_t)node * 2], y0 = U4[(size_t)node * 2 + 1];
        aB[0] = fmaf(sw, x0.x, aB[0]); aB[1] = fmaf(sw, x0.y, aB[1]);
        aB[2] = fmaf(sw, x0.z, aB[2]); aB[3] = fmaf(sw, x0.w, aB[3]);
        aB[4] = fmaf(sw, y0.x, aB[4]); aB[5] = fmaf(sw, y0.y, aB[5]);
        aB[6] = fmaf(sw, y0.z, aB[6]); aB[7] = fmaf(sw, y0.w, aB[7]);
    }
    float4 o0, o1;
    o0.x = aA[0] + aB[0]; o0.y = aA[1] + aB[1];
    o0.z = aA[2] + aB[2]; o0.w = aA[3] + aB[3];
    o1.x = aA[4] + aB[4]; o1.y = aA[5] + aB[5];
    o1.z = aA[6] + aB[6]; o1.w = aA[7] + aB[7];
    if (bias) {
        float4 b0 = ((const float4*)bias)[0];
        float4 b1 = ((const float4*)bias)[1];
        o0.x += b0.x; o0.y += b0.y; o0.z += b0.z; o0.w += b0.w;
        o1.x += b1.x; o1.y += b1.y; o1.z += b1.z; o1.w += b1.w;
    }
    if (relu) {
        o0.x = fmaxf(o0.x, 0.f); o0.y = fmaxf(o0.y, 0.f);
        o0.z = fmaxf(o0.z, 0.f); o0.w = fmaxf(o0.w, 0.f);
        o1.x = fmaxf(o1.x, 0.f); o1.y = fmaxf(o1.y, 0.f);
        o1.z = fmaxf(o1.z, 0.f); o1.w = fmaxf(o1.w, 0.f);
    }
    ((float4*)out)[(size_t)node * 2]     = o0;
    ((float4*)out)[(size_t)node * 2 + 1] = o1;
}

// width-2 gather: thread per node
__global__ void k_agg2(const float* __restrict__ u, const EdgeRec* __restrict__ edges,
                       const int* __restrict__ rowoff, const int* __restrict__ rowend,
                       const float* __restrict__ dis,
                       const float* __restrict__ bias,
                       float* __restrict__ out, int N) {
    int node = blockIdx.x * blockDim.x + threadIdx.x;
    if (node >= N) return;
    float a0 = 0.f, a1 = 0.f, b0 = 0.f, b1 = 0.f;
    int e = rowoff[node], e1 = rowend[node];
    const float2* U2 = (const float2*)u;
    for (; e + 2 <= e1; e += 2) {
        u64 er0 = *(const u64*)(edges + e);
        u64 er1 = *(const u64*)(edges + e + 1);
        int s0 = (int)(u32)er0; float w0 = __uint_as_float((u32)(er0 >> 32));
        int s1 = (int)(u32)er1; float w1 = __uint_as_float((u32)(er1 >> 32));
        float2 q0 = U2[s0];
        float2 q1 = U2[s1];
        a0 = fmaf(w0, q0.x, a0); a1 = fmaf(w0, q0.y, a1);
        b0 = fmaf(w1, q1.x, b0); b1 = fmaf(w1, q1.y, b1);
    }
    for (; e < e1; e++) {
        u64 er = *(const u64*)(edges + e);
        int s = (int)(u32)er; float wv = __uint_as_float((u32)(er >> 32));
        float2 q = U2[s];
        a0 = fmaf(wv, q.x, a0); a1 = fmaf(wv, q.y, a1);
    }
    {
        float dv = dis[node];
        float sw = dv * dv;
        float2 q = U2[node];
        b0 = fmaf(sw, q.x, b0); b1 = fmaf(sw, q.y, b1);
    }
    float2 o;
    o.x = a0 + b0 + bias[0];
    o.y = a1 + b1 + bias[1];
    ((float2*)out)[node] = o;
}

// head mm 64->32: register-blocked FFMA2, tile 96 rows x 32 cols, 96 threads
__global__ void __launch_bounds__(96) k_mmh1(const float* __restrict__ A,
                                             const float* __restrict__ W,
                                             float* __restrict__ C, int N) {
    __shared__ float As[96][65];
    __shared__ float Ws[64][32];
    int tid = threadIdx.x;
    int row0 = blockIdx.x * 96;
    {
        const float4* Wv = (const float4*)W;
        float4* Wsv = (float4*)&Ws[0][0];
        for (int i = tid; i < 512; i += 96) Wsv[i] = Wv[i];
    }
    for (int i = tid; i < 96 * 16; i += 96) {
        int r = i >> 4, kq = i & 15;
        int row = row0 + r;
        float4 v = make_float4(0.f, 0.f, 0.f, 0.f);
        if (row < N) v = ((const float4*)A)[(size_t)row * 16 + kq];
        As[r][kq * 4 + 0] = v.x;
        As[r][kq * 4 + 1] = v.y;
        As[r][kq * 4 + 2] = v.z;
        As[r][kq * 4 + 3] = v.w;
    }
    __syncthreads();

    int tx = tid & 3, ty = tid >> 2;
    u64 acc2[4][4];
#pragma unroll
    for (int i = 0; i < 4; i++)
#pragma unroll
        for (int j = 0; j < 4; j++) acc2[i][j] = 0ull;

#pragma unroll 8
    for (int k = 0; k < 64; k++) {
        u64 ad[4];
#pragma unroll
        for (int i = 0; i < 4; i++) {
            float a = As[ty * 4 + i][k];
            ad[i] = pack2(a, a);
        }
        const u64* wp = (const u64*)&Ws[k][tx * 8];
        u64 w0 = wp[0], w1 = wp[1], w2 = wp[2], w3 = wp[3];
#pragma unroll
        for (int i = 0; i < 4; i++) {
            ffma2(acc2[i][0], ad[i], w0);
            ffma2(acc2[i][1], ad[i], w1);
            ffma2(acc2[i][2], ad[i], w2);
            ffma2(acc2[i][3], ad[i], w3);
        }
    }
#pragma unroll
    for (int i = 0; i < 4; i++) {
        int row = row0 + ty * 4 + i;
        if (row >= N) continue;
        float c[8];
#pragma unroll
        for (int j = 0; j < 4; j++) unpack2(acc2[i][j], c[2 * j], c[2 * j + 1]);
        ((float4*)C)[(size_t)row * 8 + tx * 2 + 0] = make_float4(c[0], c[1], c[2], c[3]);
        ((float4*)C)[(size_t)row * 8 + tx * 2 + 1] = make_float4(c[4], c[5], c[6], c[7]);
    }
}

// head mm 32->8: warp per node; lane = (k-chunk c)*8 + col j; shfl reduce
__global__ void k_mm32x8(const float* __restrict__ A, const float* __restrict__ W,
                         float* __restrict__ C, int N) {
    __shared__ float Ws[32 * 8];
    int tid = threadIdx.x;
    for (int i = tid; i < 256; i += blockDim.x) Ws[i] = W[i];
    __syncthreads();
    int node = blockIdx.x * 8 + (tid >> 5);
    int lane = tid & 31;
    if (node >= N) return;
    int j = lane & 7, c = lane >> 3;
    const float4* ap = (const float4*)(A + (size_t)node * 32 + c * 8);
    float4 q0 = ap[0], q1 = ap[1];
    float av[8] = {q0.x, q0.y, q0.z, q0.w, q1.x, q1.y, q1.z, q1.w};
    float acc = 0.f;
#pragma unroll
    for (int kk = 0; kk < 8; kk++)
        acc = fmaf(av[kk], Ws[(c * 8 + kk) * 8 + j], acc);
    acc += __shfl_xor_sync(0xffffffffu, acc, 8);
    acc += __shfl_xor_sync(0xffffffffu, acc, 16);
    if (lane < 8) C[(size_t)node * 8 + j] = acc;
}

// head mm 8->2: thread per node
__global__ void k_mm8x2(const float* __restrict__ A, const float* __restrict__ W,
                        float* __restrict__ C, int N) {
    int node = blockIdx.x * blockDim.x + threadIdx.x;
    if (node >= N) return;
    const float4* ap = (const float4*)(A + (size_t)node * 8);
    float4 q0 = ap[0], q1 = ap[1];
    float av[8] = {q0.x, q0.y, q0.z, q0.w, q1.x, q1.y, q1.z, q1.w};
    float c0 = 0.f, c1 = 0.f;
#pragma unroll
    for (int kk = 0; kk < 8; kk++) {
        float w0 = __ldg(W + kk * 2);
        float w1 = __ldg(W + kk * 2 + 1);
        c0 = fmaf(av[kk], w0, c0);
        c1 = fmaf(av[kk], w1, c1);
    }
    ((float2*)C)[node] = make_float2(c0, c1);
}

// =============== tensor-core matmul (main loop) ===============
template <int RECALL>
__global__ void __launch_bounds__(256) k_mmTC(
    const __half* __restrict__ A16, const __half* __restrict__ W16,
    const float* __restrict__ Wx, const float* __restrict__ brv,
    const float* __restrict__ aggx,
    float* __restrict__ out32, __half* __restrict__ out16, int N) {
    __shared__ __align__(32) __half Ws[64 * 64];
    __shared__ __align__(32) float stage[128 * 64];
    int tid = threadIdx.x;
    int warp = tid >> 5;
    int row0 = blockIdx.x * 128;

    {
        const uint4* src = (const uint4*)W16;
        uint4* dst = (uint4*)Ws;
        for (int i = tid; i < 512; i += 256) dst[i] = src[i];
    }
    __syncthreads();

    wmma::fragment<wmma::accumulator, 16, 16, 16, float> acc[4];
#pragma unroll
    for (int nt = 0; nt < 4; nt++) wmma::fill_fragment(acc[nt], 0.f);

    const __half* Abase = A16 + (size_t)(row0 + warp * 16) * 64;
#pragma unroll
    for (int kt = 0; kt < 4; kt++) {
        wmma::fragment<wmma::matrix_a, 16, 16, 16, __half, wmma::row_major> af;
        wmma::load_matrix_sync(af, Abase + kt * 16, 64);
#pragma unroll
        for (int nt = 0; nt < 4; nt++) {
            wmma::fragment<wmma::matrix_b, 16, 16, 16, __half, wmma::row_major> bf;
            wmma::load_matrix_sync(bf, Ws + kt * 16 * 64 + nt * 16, 64);
            wmma::mma_sync(acc[nt], af, bf, acc[nt]);
        }
    }
#pragma unroll
    for (int nt = 0; nt < 4; nt++)
        wmma::store_matrix_sync(stage + warp * 16 * 64 + nt * 16, acc[nt], 64,
                                wmma::mem_row_major);
    __syncthreads();

    for (int i = tid; i < 128 * 16; i += 256) {
        int row = i >> 4;
        int q = i & 15;
        int grow = row0 + row;
        if (grow >= N) break;
        float4 c = ((const float4*)stage)[i];
        if (RECALL) {
            float a0 = aggx[grow * 3], a1 = aggx[grow * 3 + 1], a2 = aggx[grow * 3 + 2];
            int col = q * 4;
#pragma unroll
            for (int jj = 0; jj < 4; jj++) {
                float add = fmaf(a0, Wx[col + jj],
                             fmaf(a1, Wx[64 + col + jj],
                              fmaf(a2, Wx[128 + col + jj], brv[col + jj])));
                (&c.x)[jj] += add;
            }
            ((float4*)out32)[(size_t)grow * 16 + q] = c;
        }
        uint2 m;
        m.x = f2h(c.x, c.y);
        m.y = f2h(c.z, c.w);
        ((uint2*)out16)[(size_t)grow * 16 + q] = m;
    }
}

// =============== host launch ===============

extern "C" void kernel_launch(void* const* d_in, const int* in_sizes, int n_in,
                              void* d_out, int out_size) {
    const float* x   = (const float*)d_in[0];
    const float* Wp  = (const float*)d_in[1];
    const float* bp  = (const float*)d_in[2];
    const float* Wr  = (const float*)d_in[3];
    const float* br  = (const float*)d_in[4];
    const float* W11 = (const float*)d_in[5];
    const float* b11 = (const float*)d_in[6];
    const float* W12 = (const float*)d_in[7];
    const float* b12 = (const float*)d_in[8];
    const float* W21 = (const float*)d_in[9];
    const float* b21 = (const float*)d_in[10];
    const float* W22 = (const float*)d_in[11];
    const float* b22 = (const float*)d_in[12];
    const float* Wh1 = (const float*)d_in[13];
    const float* bh1 = (const float*)d_in[14];
    const float* Wh2 = (const float*)d_in[15];
    const float* bh2 = (const float*)d_in[16];
    const float* Wh3 = (const float*)d_in[17];
    const float* bh3 = (const float*)d_in[18];
    const int*   ei  = (const int*)d_in[19];

    int N = in_sizes[0] / 3;
    int E = in_sizes[19] / 2;
    const int* esrc = ei;
    const int* edst = ei + E;

    int *zero, *rowoff, *rowend;
    float *dis, *aggx;
    EdgeRec* edges;
    float4 *t4, *u4, *v4;
    uint4 *t16p, *u16p, *v16p, *w16p;
    cudaGetSymbolAddress((void**)&zero, g_zero);
    cudaGetSymbolAddress((void**)&rowoff, g_rowoff);
    cudaGetSymbolAddress((void**)&rowend, g_rowend);
    cudaGetSymbolAddress((void**)&dis, g_dis);
    cudaGetSymbolAddress((void**)&edges, g_edges);
    cudaGetSymbolAddress((void**)&aggx, g_aggx);
    cudaGetSymbolAddress((void**)&t4, g_t);
    cudaGetSymbolAddress((void**)&u4, g_u);
    cudaGetSymbolAddress((void**)&v4, g_v);
    cudaGetSymbolAddress((void**)&t16p, g_t16);
    cudaGetSymbolAddress((void**)&u16p, g_u16);
    cudaGetSymbolAddress((void**)&v16p, g_v16);
    cudaGetSymbolAddress((void**)&w16p, g_w16);
    int* counts = zero;
    int* cursor = zero + NCAP;
    int* total  = zero + 2 * NCAP;
    float* t = (float*)t4;
    float* u = (float*)u4;
    float* v = (float*)v4;
    __half* t16 = (__half*)t16p;
    __half* u16 = (__half*)u16p;
    __half* v16 = (__half*)v16p;
    __half* w16 = (__half*)w16p;
    __half* Wr16   = w16;
    __half* W11_16 = w16 + 4096;
    __half* W12_16 = w16 + 2 * 4096;
    __half* W21_16 = w16 + 3 * 4096;
    __half* W22_16 = w16 + 4 * 4096;

    int nbE = (E + 255) / 256;
    int nbN = (N + 255) / 256;
    int nbWarp = (N + 7) / 8;       // 8 nodes per 256-thread block
    int nbAgg = (N + 15) / 16;      // half-warp agg: 16 nodes per block
    int nbTC = (N + 127) / 128;     // tensor-core mm tiles
    int nbMMH = (N + 95) / 96;      // head mm1 tiles

    // ---- graph setup (5 launches) ----
    cudaMemsetAsync(zero, 0, (size_t)(2 * NCAP + 4) * sizeof(int), 0);
    k_count<<<nbE, 256>>>(edst, E, counts);
    k_setup2<<<nbN, 256>>>(counts, dis, rowoff, rowend, total, N,
                           Wr, W11, W12, W21, W22, w16);
    k_fill<<<nbE, 256>>>(esrc, edst, E, rowoff, cursor, dis, edges);
    k_aggx_proj<<<nbWarp, 256>>>(x, edges, rowoff, rowend, dis,
                                 Wp, bp, aggx, t, t16, N);

    const float* Wrx = Wr + 64 * 64;  // rows 64..66 of Wr (x part)

    // ---- iterations ----
    for (int it = 0; it < ITERS; it++) {
        k_aggv<0, 0, 0><<<nbAgg, 256>>>((uint2*)t16, edges, rowoff, rowend, dis,
                                        nullptr, nullptr, nullptr, (uint2*)v16, N);
        k_mmTC<1><<<nbTC, 256>>>(v16, Wr16, Wrx, br, aggx, t, t16, N);
        // block 1
        k_mmTC<0><<<nbTC, 256>>>(t16, W11_16, nullptr, nullptr, nullptr,
                                 nullptr, u16, N);
        k_aggv<1, 0, 0><<<nbAgg, 256>>>((uint2*)u16, edges, rowoff, rowend, dis,
                                        b11, nullptr, nullptr, (uint2*)v16, N);
        k_mmTC<0><<<nbTC, 256>>>(v16, W12_16, nullptr, nullptr, nullptr,
                                 nullptr, u16, N);
        k_aggv<1, 1, 1><<<nbAgg, 256>>>((uint2*)u16, edges, rowoff, rowend, dis,
                                        b12, t, t, (uint2*)t16, N);
        // block 2
        k_mmTC<0><<<nbTC, 256>>>(t16, W21_16, nullptr, nullptr, nullptr,
                                 nullptr, u16, N);
        k_aggv<1, 0, 0><<<nbAgg, 256>>>((uint2*)u16, edges, rowoff, rowend, dis,
                                        b21, nullptr, nullptr, (uint2*)v16, N);
        k_mmTC<0><<<nbTC, 256>>>(v16, W22_16, nullptr, nullptr, nullptr,
                                 nullptr, u16, N);
        k_aggv<1, 1, 1><<<nbAgg, 256>>>((uint2*)u16, edges, rowoff, rowend, dis,
                                        b22, t, t, (uint2*)t16, N);
    }

    // ---- head (fp32, optimized kernels) ----
    k_mmh1<<<nbMMH, 96>>>(t, Wh1, u, N);
    k_agg32<<<nbWarp, 256>>>(u, edges, rowoff, rowend, dis, bh1, 1, v, N);
    k_mm32x8<<<nbWarp, 256>>>(v, Wh2, u, N);
    k_agg8<<<nbN, 256>>>(u, edges, rowoff, rowend, dis, bh2, 1, v, N);
    k_mm8x2<<<nbN, 256>>>(v, Wh3, u, N);
    k_agg2<<<nbN, 256>>>(u, edges, rowoff, rowend, dis, bh3, (float*)d_out, N);
}

// round 17
// speedup vs baseline: 1.1261x; 1.0016x over previous
#include <cuda_runtime.h>
#include <cuda_fp16.h>
#include <mma.h>
#include <math.h>

using namespace nvcuda;

// Problem-fixed capacities (dataset constants)
#define NCAP 100000
#define NPAD (NCAP + 128)
#define ECAP 1600000
#define ITERS 5

struct __align__(8) EdgeRec { int src; float w; };
typedef unsigned long long u64;
typedef unsigned int u32;

// ---- static device scratch (no allocation allowed) ----
// zero region: [counts | cursor | total]
__device__ int     g_zero[2 * NCAP + 4];
__device__ int     g_rowoff[NCAP];
__device__ int     g_rowend[NCAP];
__device__ float   g_dis[NCAP];
__device__ EdgeRec g_edges[ECAP];
__device__ float   g_aggx[NCAP * 3];
__device__ float4  g_t[NCAP * 16];
__device__ float4  g_u[NCAP * 16];
__device__ float4  g_v[NCAP * 16];
// fp16 mirrors, padded (64 halfs = 16 uint2 per node)
__device__ uint4   g_t16[NPAD * 8];
__device__ uint4   g_u16[NPAD * 8];
__device__ uint4   g_v16[NPAD * 8];
// fp16 weights: Wr_t, W11, W12, W21, W22 (each 64x64)
__device__ uint4   g_w16[5 * 4096 / 8];

// ---- packed fp32x2 helpers ----
__device__ __forceinline__ u64 pack2(float x, float y) {
    u64 r; asm("mov.b64 %0, {%1, %2};" : "=l"(r) : "f"(x), "f"(y)); return r;
}
__device__ __forceinline__ void unpack2(u64 v, float& x, float& y) {
    asm("mov.b64 {%0, %1}, %2;" : "=f"(x), "=f"(y) : "l"(v));
}
__device__ __forceinline__ void ffma2(u64& d, u64 a, u64 b) {
    asm("fma.rn.f32x2 %0, %1, %2, %0;" : "+l"(d) : "l"(a), "l"(b));
}

// ---- fp16 pack/unpack ----
__device__ __forceinline__ float2 h2f(u32 q) {
    __half2 h = *reinterpret_cast<__half2*>(&q);
    return __half22float2(h);
}
__device__ __forceinline__ u32 f2h(float x, float y) {
    __half2 h = __floats2half2_rn(x, y);
    return *reinterpret_cast<u32*>(&h);
}

// =============== graph setup kernels ===============

__global__ void k_count(const int* __restrict__ dst, int E, int* __restrict__ counts) {
    int i = blockIdx.x * blockDim.x + threadIdx.x;
    if (i < E) atomicAdd(&counts[dst[i]], 1);
}

__global__ void k_setup2(const int* __restrict__ counts, float* __restrict__ dis,
                         int* __restrict__ rowoff, int* __restrict__ rowend,
                         int* __restrict__ total, int N,
                         const float* __restrict__ Wr, const float* __restrict__ W11,
                         const float* __restrict__ W12, const float* __restrict__ W21,
                         const float* __restrict__ W22, __half* __restrict__ w16) {
    int i = blockIdx.x * blockDim.x + threadIdx.x;
    if (i < 4096) {
        w16[i]            = __float2half_rn(Wr[i]);
        w16[4096 + i]     = __float2half_rn(W11[i]);
        w16[2 * 4096 + i] = __float2half_rn(W12[i]);
        w16[3 * 4096 + i] = __float2half_rn(W21[i]);
        w16[4 * 4096 + i] = __float2half_rn(W22[i]);
    }
    if (i < N) {
        int c = counts[i];
        dis[i] = rsqrtf((float)(c + 1));
        int off = atomicAdd(total, c);
        rowoff[i] = off;
        rowend[i] = off + c;
    }
}

__global__ void k_fill(const int* __restrict__ srcA, const int* __restrict__ dstA, int E,
                       const int* __restrict__ rowoff, int* __restrict__ cursor,
                       const float* __restrict__ dis, EdgeRec* __restrict__ edges) {
    int i = blockIdx.x * blockDim.x + threadIdx.x;
    if (i >= E) return;
    int s = srcA[i], d = dstA[i];
    int pos = rowoff[d] + atomicAdd(&cursor[d], 1);
    EdgeRec r;
    r.src = s;
    r.w = dis[s] * dis[d];
    edges[pos] = r;
}

// fused: aggx = agg(x) + projection
__global__ void k_aggx_proj(const float* __restrict__ x, const EdgeRec* __restrict__ edges,
                            const int* __restrict__ rowoff, const int* __restrict__ rowend,
                            const float* __restrict__ dis,
                            const float* __restrict__ Wp, const float* __restrict__ bp,
                            float* __restrict__ aggx, float* __restrict__ t,
                            __half* __restrict__ t16, int N) {
    int node = blockIdx.x * 8 + (threadIdx.x >> 5);
    int lane = threadIdx.x & 31;
    if (node >= N) return;
    float a0 = 0.f, a1 = 0.f, a2 = 0.f;
    int e0 = rowoff[node], e1 = rowend[node];
    for (int e = e0 + lane; e < e1; e += 32) {
        EdgeRec r = edges[e];
        const float* xp = x + (size_t)r.src * 3;
        a0 = fmaf(r.w, __ldg(xp), a0);
        a1 = fmaf(r.w, __ldg(xp + 1), a1);
        a2 = fmaf(r.w, __ldg(xp + 2), a2);
    }
    if (lane == 0) {
        float dv = dis[node];
        float sw = dv * dv;
        const float* xp = x + (size_t)node * 3;
        a0 = fmaf(sw, xp[0], a0);
        a1 = fmaf(sw, xp[1], a1);
        a2 = fmaf(sw, xp[2], a2);
    }
#pragma unroll
    for (int off = 16; off > 0; off >>= 1) {
        a0 += __shfl_xor_sync(0xffffffffu, a0, off);
        a1 += __shfl_xor_sync(0xffffffffu, a1, off);
        a2 += __shfl_xor_sync(0xffffffffu, a2, off);
    }
    if (lane == 0) {
        aggx[node * 3] = a0;
        aggx[node * 3 + 1] = a1;
        aggx[node * 3 + 2] = a2;
    }
#pragma unroll
    for (int jj = 0; jj < 2; jj++) {
        int j = 2 * lane + jj;
        float acc = bp[j];
        acc = fmaf(a0, Wp[j], acc);
        acc = fmaf(a1, Wp[64 + j], acc);
        acc = fmaf(a2, Wp[128 + j], acc);
        acc = fmaxf(acc, 0.f);
        t[(size_t)node * 64 + j] = acc;
        t16[(size_t)node * 64 + j] = __float2half_rn(acc);
    }
}

// =============== main aggregation: half-warp gather, 8-deep unroll ===============
template <int RELU, int RES, int W32>
__global__ void __launch_bounds__(256) k_aggv(
    const uint2* __restrict__ U16, const EdgeRec* __restrict__ edges,
    const int* __restrict__ rowoff, const int* __restrict__ rowend,
    const float* __restrict__ dis,
    const float* __restrict__ bias, const float* __restrict__ res,
    float* __restrict__ out, uint2* __restrict__ out16, int N) {
    int tid = threadIdx.x;
    int warp = tid >> 5;
    int half = (tid >> 4) & 1;
    int sub = tid & 15;
    int node = blockIdx.x * 16 + warp * 2 + half;
    if (node >= N) return;

    float ac0[4] = {0.f, 0.f, 0.f, 0.f};
    float ac1[4] = {0.f, 0.f, 0.f, 0.f};
    float ac2[4] = {0.f, 0.f, 0.f, 0.f};
    float ac3[4] = {0.f, 0.f, 0.f, 0.f};

    int e = rowoff[node];
    int e1 = rowend[node];
    for (; e + 8 <= e1; e += 8) {
        u64 er0 = *(const u64*)(edges + e);
        u64 er1 = *(const u64*)(edges + e + 1);
        u64 er2 = *(const u64*)(edges + e + 2);
        u64 er3 = *(const u64*)(edges + e + 3);
        u64 er4 = *(const u64*)(edges + e + 4);
        u64 er5 = *(const u64*)(edges + e + 5);
        u64 er6 = *(const u64*)(edges + e + 6);
        u64 er7 = *(const u64*)(edges + e + 7);
        int s0 = (int)(u32)er0; float w0 = __uint_as_float((u32)(er0 >> 32));
        int s1 = (int)(u32)er1; float w1 = __uint_as_float((u32)(er1 >> 32));
        int s2 = (int)(u32)er2; float w2 = __uint_as_float((u32)(er2 >> 32));
        int s3 = (int)(u32)er3; float w3 = __uint_as_float((u32)(er3 >> 32));
        int s4 = (int)(u32)er4; float w4 = __uint_as_float((u32)(er4 >> 32));
        int s5 = (int)(u32)er5; float w5 = __uint_as_float((u32)(er5 >> 32));
        int s6 = (int)(u32)er6; float w6 = __uint_as_float((u32)(er6 >> 32));
        int s7 = (int)(u32)er7; float w7 = __uint_as_float((u32)(er7 >> 32));
        uint2 q0 = U16[(size_t)s0 * 16 + sub];
        uint2 q1 = U16[(size_t)s1 * 16 + sub];
        uint2 q2 = U16[(size_t)s2 * 16 + sub];
        uint2 q3 = U16[(size_t)s3 * 16 + sub];
        uint2 q4 = U16[(size_t)s4 * 16 + sub];
        uint2 q5 = U16[(size_t)s5 * 16 + sub];
        uint2 q6 = U16[(size_t)s6 * 16 + sub];
        uint2 q7 = U16[(size_t)s7 * 16 + sub];
        {
            float2 fa = h2f(q0.x), fb = h2f(q0.y);
            ac0[0] = fmaf(w0, fa.x, ac0[0]); ac0[1] = fmaf(w0, fa.y, ac0[1]);
            ac0[2] = fmaf(w0, fb.x, ac0[2]); ac0[3] = fmaf(w0, fb.y, ac0[3]);
        }
        {
            float2 fa = h2f(q1.x), fb = h2f(q1.y);
            ac1[0] = fmaf(w1, fa.x, ac1[0]); ac1[1] = fmaf(w1, fa.y, ac1[1]);
            ac1[2] = fmaf(w1, fb.x, ac1[2]); ac1[3] = fmaf(w1, fb.y, ac1[3]);
        }
        {
            float2 fa = h2f(q2.x), fb = h2f(q2.y);
            ac2[0] = fmaf(w2, fa.x, ac2[0]); ac2[1] = fmaf(w2, fa.y, ac2[1]);
            ac2[2] = fmaf(w2, fb.x, ac2[2]); ac2[3] = fmaf(w2, fb.y, ac2[3]);
        }
        {
            float2 fa = h2f(q3.x), fb = h2f(q3.y);
            ac3[0] = fmaf(w3, fa.x, ac3[0]); ac3[1] = fmaf(w3, fa.y, ac3[1]);
            ac3[2] = fmaf(w3, fb.x, ac3[2]); ac3[3] = fmaf(w3, fb.y, ac3[3]);
        }
        {
            float2 fa = h2f(q4.x), fb = h2f(q4.y);
            ac0[0] = fmaf(w4, fa.x, ac0[0]); ac0[1] = fmaf(w4, fa.y, ac0[1]);
            ac0[2] = fmaf(w4, fb.x, ac0[2]); ac0[3] = fmaf(w4, fb.y, ac0[3]);
        }
        {
            float2 fa = h2f(q5.x), fb = h2f(q5.y);
            ac1[0] = fmaf(w5, fa.x, ac1[0]); ac1[1] = fmaf(w5, fa.y, ac1[1]);
            ac1[2] = fmaf(w5, fb.x, ac1[2]); ac1[3] = fmaf(w5, fb.y, ac1[3]);
        }
        {
            float2 fa = h2f(q6.x), fb = h2f(q6.y);
            ac2[0] = fmaf(w6, fa.x, ac2[0]); ac2[1] = fmaf(w6, fa.y, ac2[1]);
            ac2[2] = fmaf(w6, fb.x, ac2[2]); ac2[3] = fmaf(w6, fb.y, ac2[3]);
        }
        {
            float2 fa = h2f(q7.x), fb = h2f(q7.y);
            ac3[0] = fmaf(w7, fa.x, ac3[0]); ac3[1] = fmaf(w7, fa.y, ac3[1]);
            ac3[2] = fmaf(w7, fb.x, ac3[2]); ac3[3] = fmaf(w7, fb.y, ac3[3]);
        }
    }
    for (; e + 4 <= e1; e += 4) {
        u64 er0 = *(const u64*)(edges + e);
        u64 er1 = *(const u64*)(edges + e + 1);
        u64 er2 = *(const u64*)(edges + e + 2);
        u64 er3 = *(const u64*)(edges + e + 3);
        int s0 = (int)(u32)er0; float w0 = __uint_as_float((u32)(er0 >> 32));
        int s1 = (int)(u32)er1; float w1 = __uint_as_float((u32)(er1 >> 32));
        int s2 = (int)(u32)er2; float w2 = __uint_as_float((u32)(er2 >> 32));
        int s3 = (int)(u32)er3; float w3 = __uint_as_float((u32)(er3 >> 32));
        uint2 q0 = U16[(size_t)s0 * 16 + sub];
        uint2 q1 = U16[(size_t)s1 * 16 + sub];
        uint2 q2 = U16[(size_t)s2 * 16 + sub];
        uint2 q3 = U16[(size_t)s3 * 16 + sub];
        float2 f0a = h2f(q0.x), f0b = h2f(q0.y);
        float2 f1a = h2f(q1.x), f1b = h2f(q1.y);
        float2 f2a = h2f(q2.x), f2b = h2f(q2.y);
        float2 f3a = h2f(q3.x), f3b = h2f(q3.y);
        ac0[0] = fmaf(w0, f0a.x, ac0[0]); ac0[1] = fmaf(w0, f0a.y, ac0[1]);
        ac0[2] = fmaf(w0, f0b.x, ac0[2]); ac0[3] = fmaf(w0, f0b.y, ac0[3]);
        ac1[0] = fmaf(w1, f1a.x, ac1[0]); ac1[1] = fmaf(w1, f1a.y, ac1[1]);
        ac1[2] = fmaf(w1, f1b.x, ac1[2]); ac1[3] = fmaf(w1, f1b.y, ac1[3]);
        ac2[0] = fmaf(w2, f2a.x, ac2[0]); ac2[1] = fmaf(w2, f2a.y, ac2[1]);
        ac2[2] = fmaf(w2, f2b.x, ac2[2]); ac2[3] = fmaf(w2, f2b.y, ac2[3]);
        ac3[0] = fmaf(w3, f3a.x, ac3[0]); ac3[1] = fmaf(w3, f3a.y, ac3[1]);
        ac3[2] = fmaf(w3, f3b.x, ac3[2]); ac3[3] = fmaf(w3, f3b.y, ac3[3]);
    }
    for (; e < e1; e++) {
        u64 er = *(const u64*)(edges + e);
        int s = (int)(u32)er; float wv = __uint_as_float((u32)(er >> 32));
        uint2 q = U16[(size_t)s * 16 + sub];
        float2 fa = h2f(q.x), fb = h2f(q.y);
        ac0[0] = fmaf(wv, fa.x, ac0[0]); ac0[1] = fmaf(wv, fa.y, ac0[1]);
        ac0[2] = fmaf(wv, fb.x, ac0[2]); ac0[3] = fmaf(wv, fb.y, ac0[3]);
    }
    // self loop
    {
        float dv = dis[node];
        float sw = dv * dv;
        uint2 q = U16[(size_t)node * 16 + sub];
        float2 fa = h2f(q.x), fb = h2f(q.y);
        ac1[0] = fmaf(sw, fa.x, ac1[0]); ac1[1] = fmaf(sw, fa.y, ac1[1]);
        ac1[2] = fmaf(sw, fb.x, ac1[2]); ac1[3] = fmaf(sw, fb.y, ac1[3]);
    }
    float4 o;
    o.x = (ac0[0] + ac1[0]) + (ac2[0] + ac3[0]);
    o.y = (ac0[1] + ac1[1]) + (ac2[1] + ac3[1]);
    o.z = (ac0[2] + ac1[2]) + (ac2[2] + ac3[2]);
    o.w = (ac0[3] + ac1[3]) + (ac2[3] + ac3[3]);
    if (bias) {
        float4 b = ((const float4*)bias)[sub];
        o.x += b.x; o.y += b.y; o.z += b.z; o.w += b.w;
    }
    if (RES) {
        float4 rr = ((const float4*)res)[(size_t)node * 16 + sub];
        o.x += rr.x; o.y += rr.y; o.z += rr.z; o.w += rr.w;
    }
    if (RELU) {
        o.x = fmaxf(o.x, 0.f); o.y = fmaxf(o.y, 0.f);
        o.z = fmaxf(o.z, 0.f); o.w = fmaxf(o.w, 0.f);
    }
    if (W32) ((float4*)out)[(size_t)node * 16 + sub] = o;
    {
        uint2 m;
        m.x = f2h(o.x, o.y);
        m.y = f2h(o.z, o.w);
        out16[(size_t)node * 16 + sub] = m;
    }
}

// =============== head kernels (fp32, optimized) ===============

// width-32 gather: warp per node, 4-deep unroll
__global__ void k_agg32(const float* __restrict__ u, const EdgeRec* __restrict__ edges,
                        const int* __restrict__ rowoff, const int* __restrict__ rowend,
                        const float* __restrict__ dis,
                        const float* __restrict__ bias, int relu,
                        float* __restrict__ out, int N) {
    int node = blockIdx.x * 8 + (threadIdx.x >> 5);
    int lane = threadIdx.x & 31;
    if (node >= N) return;
    float a0 = 0.f, a1 = 0.f, a2 = 0.f, a3 = 0.f;
    int e = rowoff[node], e1 = rowend[node];
    for (; e + 4 <= e1; e += 4) {
        u64 er0 = *(const u64*)(edges + e);
        u64 er1 = *(const u64*)(edges + e + 1);
        u64 er2 = *(const u64*)(edges + e + 2);
        u64 er3 = *(const u64*)(edges + e + 3);
        int s0 = (int)(u32)er0; float w0 = __uint_as_float((u32)(er0 >> 32));
        int s1 = (int)(u32)er1; float w1 = __uint_as_float((u32)(er1 >> 32));
        int s2 = (int)(u32)er2; float w2 = __uint_as_float((u32)(er2 >> 32));
        int s3 = (int)(u32)er3; float w3 = __uint_as_float((u32)(er3 >> 32));
        float f0 = u[(size_t)s0 * 32 + lane];
        float f1 = u[(size_t)s1 * 32 + lane];
        float f2 = u[(size_t)s2 * 32 + lane];
        float f3 = u[(size_t)s3 * 32 + lane];
        a0 = fmaf(w0, f0, a0);
        a1 = fmaf(w1, f1, a1);
        a2 = fmaf(w2, f2, a2);
        a3 = fmaf(w3, f3, a3);
    }
    for (; e < e1; e++) {
        u64 er = *(const u64*)(edges + e);
        int s = (int)(u32)er; float wv = __uint_as_float((u32)(er >> 32));
        a0 = fmaf(wv, u[(size_t)s * 32 + lane], a0);
    }
    float dv = dis[node];
    a1 = fmaf(dv * dv, u[(size_t)node * 32 + lane], a1);
    float acc = (a0 + a1) + (a2 + a3);
    if (bias) acc += bias[lane];
    if (relu) acc = fmaxf(acc, 0.f);
    out[(size_t)node * 32 + lane] = acc;
}

// width-8 gather: thread per node, float4 loads, 2-edge unroll
__global__ void k_agg8(const float* __restrict__ u, const EdgeRec* __restrict__ edges,
                       const int* __restrict__ rowoff, const int* __restrict__ rowend,
                       const float* __restrict__ dis,
                       const float* __restrict__ bias, int relu,
                       float* __restrict__ out, int N) {
    int node = blockIdx.x * blockDim.x + threadIdx.x;
    if (node >= N) return;
    float aA[8] = {0.f, 0.f, 0.f, 0.f, 0.f, 0.f, 0.f, 0.f};
    float aB[8] = {0.f, 0.f, 0.f, 0.f, 0.f, 0.f, 0.f, 0.f};
    int e = rowoff[node], e1 = rowend[node];
    const float4* U4 = (const float4*)u;
    for (; e + 2 <= e1; e += 2) {
        u64 er0 = *(const u64*)(edges + e);
        u64 er1 = *(const u64*)(edges + e + 1);
        int s0 = (int)(u32)er0; float w0 = __uint_as_float((u32)(er0 >> 32));
        int s1 = (int)(u32)er1; float w1 = __uint_as_float((u32)(er1 >> 32));
        float4 x0 = U4[(size_t)s0 * 2],     y0 = U4[(size_t)s0 * 2 + 1];
        float4 x1 = U4[(size_t)s1 * 2],     y1 = U4[(size_t)s1 * 2 + 1];
        aA[0] = fmaf(w0, x0.x, aA[0]); aA[1] = fmaf(w0, x0.y, aA[1]);
        aA[2] = fmaf(w0, x0.z, aA[2]); aA[3] = fmaf(w0, x0.w, aA[3]);
        aA[4] = fmaf(w0, y0.x, aA[4]); aA[5] = fmaf(w0, y0.y, aA[5]);
        aA[6] = fmaf(w0, y0.z, aA[6]); aA[7] = fmaf(w0, y0.w, aA[7]);
        aB[0] = fmaf(w1, x1.x, aB[0]); aB[1] = fmaf(w1, x1.y, aB[1]);
        aB[2] = fmaf(w1, x1.z, aB[2]); aB[3] = fmaf(w1, x1.w, aB[3]);
        aB[4] = fmaf(w1, y1.x, aB[4]); aB[5] = fmaf(w1, y1.y, aB[5]);
        aB[6] = fmaf(w1, y1.z, aB[6]); aB[7] = fmaf(w1, y1.w, aB[7]);
    }
    for (; e < e1; e++) {
        u64 er = *(const u64*)(edges + e);
        int s = (int)(u32)er; float wv = __uint_as_float((u32)(er >> 32));
        float4 x0 = U4[(size_t)s * 2], y0 = U4[(size_t)s * 2 + 1];
        aA[0] = fmaf(wv, x0.x, aA[0]); aA[1] = fmaf(wv, x0.y, aA[1]);
        aA[2] = fmaf(wv, x0.z, aA[2]); aA[3] = fmaf(wv, x0.w, aA[3]);
        aA[4] = fmaf(wv, y0.x, aA[4]); aA[5] = fmaf(wv, y0.y, aA[5]);
        aA[6] = fmaf(wv, y0.z, aA[6]); aA[7] = fmaf(wv, y0.w, aA[7]);
    }
    {
        float dv = dis[node];
        float sw = dv * dv;
        float4 x0 = U4[(size_t)node * 2], y0 = U4[(size_t)node * 2 + 1];
        aB[0] = fmaf(sw, x0.x, aB[0]); aB[1] = fmaf(sw, x0.y, aB[1]);
        aB[2] = fmaf(sw, x0.z, aB[2]); aB[3] = fmaf(sw, x0.w, aB[3]);
        aB[4] = fmaf(sw, y0.x, aB[4]); aB[5] = fmaf(sw, y0.y, aB[5]);
        aB[6] = fmaf(sw, y0.z, aB[6]); aB[7] = fmaf(sw, y0.w, aB[7]);
    }
    float4 o0, o1;
    o0.x = aA[0] + aB[0]; o0.y = aA[1] + aB[1];
    o0.z = aA[2] + aB[2]; o0.w = aA[3] + aB[3];
    o1.x = aA[4] + aB[4]; o1.y = aA[5] + aB[5];
    o1.z = aA[6] + aB[6]; o1.w = aA[7] + aB[7];
    if (bias) {
        float4 b0 = ((const float4*)bias)[0];
        float4 b1 = ((const float4*)bias)[1];
        o0.x += b0.x; o0.y += b0.y; o0.z += b0.z; o0.w += b0.w;
        o1.x += b1.x; o1.y += b1.y; o1.z += b1.z; o1.w += b1.w;
    }
    if (relu) {
        o0.x = fmaxf(o0.x, 0.f); o0.y = fmaxf(o0.y, 0.f);
        o0.z = fmaxf(o0.z, 0.f); o0.w = fmaxf(o0.w, 0.f);
        o1.x = fmaxf(o1.x, 0.f); o1.y = fmaxf(o1.y, 0.f);
        o1.z = fmaxf(o1.z, 0.f); o1.w = fmaxf(o1.w, 0.f);
    }
    ((float4*)out)[(size_t)node * 2]     = o0;
    ((float4*)out)[(size_t)node * 2 + 1] = o1;
}

// width-2 gather: thread per node
__global__ void k_agg2(const float* __restrict__ u, const EdgeRec* __restrict__ edges,
                       const int* __restrict__ rowoff, const int* __restrict__ rowend,
                       const float* __restrict__ dis,
                       const float* __restrict__ bias,
                       float* __restrict__ out, int N) {
    int node = blockIdx.x * blockDim.x + threadIdx.x;
    if (node >= N) return;
    float a0 = 0.f, a1 = 0.f, b0 = 0.f, b1 = 0.f;
    int e = rowoff[node], e1 = rowend[node];
    const float2* U2 = (const float2*)u;
    for (; e + 2 <= e1; e += 2) {
        u64 er0 = *(const u64*)(edges + e);
        u64 er1 = *(const u64*)(edges + e + 1);
        int s0 = (int)(u32)er0; float w0 = __uint_as_float((u32)(er0 >> 32));
        int s1 = (int)(u32)er1; float w1 = __uint_as_float((u32)(er1 >> 32));
        float2 q0 = U2[s0];
        float2 q1 = U2[s1];
        a0 = fmaf(w0, q0.x, a0); a1 = fmaf(w0, q0.y, a1);
        b0 = fmaf(w1, q1.x, b0); b1 = fmaf(w1, q1.y, b1);
    }
    for (; e < e1; e++) {
        u64 er = *(const u64*)(edges + e);
        int s = (int)(u32)er; float wv = __uint_as_float((u32)(er >> 32));
        float2 q = U2[s];
        a0 = fmaf(wv, q.x, a0); a1 = fmaf(wv, q.y, a1);
    }
    {
        float dv = dis[node];
        float sw = dv * dv;
        float2 q = U2[node];
        b0 = fmaf(sw, q.x, b0); b1 = fmaf(sw, q.y, b1);
    }
    float2 o;
    o.x = a0 + b0 + bias[0];
    o.y = a1 + b1 + bias[1];
    ((float2*)out)[node] = o;
}

// head mm 64->32: register-blocked FFMA2, tile 96 rows x 32 cols, 96 threads
__global__ void __launch_bounds__(96) k_mmh1(const float* __restrict__ A,
                                             const float* __restrict__ W,
                                             float* __restrict__ C, int N) {
    __shared__ float As[96][65];
    __shared__ float Ws[64][32];
    int tid = threadIdx.x;
    int row0 = blockIdx.x * 96;
    {
        const float4* Wv = (const float4*)W;
        float4* Wsv = (float4*)&Ws[0][0];
        for (int i = tid; i < 512; i += 96) Wsv[i] = Wv[i];
    }
    for (int i = tid; i < 96 * 16; i += 96) {
        int r = i >> 4, kq = i & 15;
        int row = row0 + r;
        float4 v = make_float4(0.f, 0.f, 0.f, 0.f);
        if (row < N) v = ((const float4*)A)[(size_t)row * 16 + kq];
        As[r][kq * 4 + 0] = v.x;
        As[r][kq * 4 + 1] = v.y;
        As[r][kq * 4 + 2] = v.z;
        As[r][kq * 4 + 3] = v.w;
    }
    __syncthreads();

    int tx = tid & 3, ty = tid >> 2;
    u64 acc2[4][4];
#pragma unroll
    for (int i = 0; i < 4; i++)
#pragma unroll
        for (int j = 0; j < 4; j++) acc2[i][j] = 0ull;

#pragma unroll 8
    for (int k = 0; k < 64; k++) {
        u64 ad[4];
#pragma unroll
        for (int i = 0; i < 4; i++) {
            float a = As[ty * 4 + i][k];
            ad[i] = pack2(a, a);
        }
        const u64* wp = (const u64*)&Ws[k][tx * 8];
        u64 w0 = wp[0], w1 = wp[1], w2 = wp[2], w3 = wp[3];
#pragma unroll
        for (int i = 0; i < 4; i++) {
            ffma2(acc2[i][0], ad[i], w0);
            ffma2(acc2[i][1], ad[i], w1);
            ffma2(acc2[i][2], ad[i], w2);
            ffma2(acc2[i][3], ad[i], w3);
        }
    }
#pragma unroll
    for (int i = 0; i < 4; i++) {
        int row = row0 + ty * 4 + i;
        if (row >= N) continue;
        float c[8];
#pragma unroll
        for (int j = 0; j < 4; j++) unpack2(acc2[i][j], c[2 * j], c[2 * j + 1]);
        ((float4*)C)[(size_t)row * 8 + tx * 2 + 0] = make_float4(c[0], c[1], c[2], c[3]);
        ((float4*)C)[(size_t)row * 8 + tx * 2 + 1] = make_float4(c[4], c[5], c[6], c[7]);
    }
}

// head mm 32->8: warp per node; lane = (k-chunk c)*8 + col j; shfl reduce
__global__ void k_mm32x8(const float* __restrict__ A, const float* __restrict__ W,
                         float* __restrict__ C, int N) {
    __shared__ float Ws[32 * 8];
    int tid = threadIdx.x;
    for (int i = tid; i < 256; i += blockDim.x) Ws[i] = W[i];
    __syncthreads();
    int node = blockIdx.x * 8 + (tid >> 5);
    int lane = tid & 31;
    if (node >= N) return;
    int j = lane & 7, c = lane >> 3;
    const float4* ap = (const float4*)(A + (size_t)node * 32 + c * 8);
    float4 q0 = ap[0], q1 = ap[1];
    float av[8] = {q0.x, q0.y, q0.z, q0.w, q1.x, q1.y, q1.z, q1.w};
    float acc = 0.f;
#pragma unroll
    for (int kk = 0; kk < 8; kk++)
        acc = fmaf(av[kk], Ws[(c * 8 + kk) * 8 + j], acc);
    acc += __shfl_xor_sync(0xffffffffu, acc, 8);
    acc += __shfl_xor_sync(0xffffffffu, acc, 16);
    if (lane < 8) C[(size_t)node * 8 + j] = acc;
}

// head mm 8->2: thread per node
__global__ void k_mm8x2(const float* __restrict__ A, const float* __restrict__ W,
                        float* __restrict__ C, int N) {
    int node = blockIdx.x * blockDim.x + threadIdx.x;
    if (node >= N) return;
    const float4* ap = (const float4*)(A + (size_t)node * 8);
    float4 q0 = ap[0], q1 = ap[1];
    float av[8] = {q0.x, q0.y, q0.z, q0.w, q1.x, q1.y, q1.z, q1.w};
    float c0 = 0.f, c1 = 0.f;
#pragma unroll
    for (int kk = 0; kk < 8; kk++) {
        float w0 = __ldg(W + kk * 2);
        float w1 = __ldg(W + kk * 2 + 1);
        c0 = fmaf(av[kk], w0, c0);
        c1 = fmaf(av[kk], w1, c1);
    }
    ((float2*)C)[node] = make_float2(c0, c1);
}

// =============== tensor-core matmul (main loop) ===============
// v2: single block barrier (after W stage). Each warp stages its own 16x64
// accumulator tile and runs its own epilogue — no second __syncthreads.
template <int RECALL>
__global__ void __launch_bounds__(256) k_mmTC(
    const __half* __restrict__ A16, const __half* __restrict__ W16,
    const float* __restrict__ Wx, const float* __restrict__ brv,
    const float* __restrict__ aggx,
    float* __restrict__ out32, __half* __restrict__ out16, int N) {
    __shared__ __align__(32) __half Ws[64 * 64];
    __shared__ __align__(32) float stage[128 * 64];
    int tid = threadIdx.x;
    int warp = tid >> 5;
    int lane = tid & 31;
    int row0 = blockIdx.x * 128;

    {
        const uint4* src = (const uint4*)W16;
        uint4* dst = (uint4*)Ws;
        for (int i = tid; i < 512; i += 256) dst[i] = src[i];
    }
    __syncthreads();

    wmma::fragment<wmma::accumulator, 16, 16, 16, float> acc[4];
#pragma unroll
    for (int nt = 0; nt < 4; nt++) wmma::fill_fragment(acc[nt], 0.f);

    const __half* Abase = A16 + (size_t)(row0 + warp * 16) * 64;
#pragma unroll
    for (int kt = 0; kt < 4; kt++) {
        wmma::fragment<wmma::matrix_a, 16, 16, 16, __half, wmma::row_major> af;
        wmma::load_matrix_sync(af, Abase + kt * 16, 64);
#pragma unroll
        for (int nt = 0; nt < 4; nt++) {
            wmma::fragment<wmma::matrix_b, 16, 16, 16, __half, wmma::row_major> bf;
            wmma::load_matrix_sync(bf, Ws + kt * 16 * 64 + nt * 16, 64);
            wmma::mma_sync(acc[nt], af, bf, acc[nt]);
        }
    }
    float* wstage = stage + warp * 16 * 64;
#pragma unroll
    for (int nt = 0; nt < 4; nt++)
        wmma::store_matrix_sync(wstage + nt * 16, acc[nt], 64,
                                wmma::mem_row_major);
    __syncwarp();

    // per-warp epilogue: this warp's 16 rows x 64 cols = 256 float4 quads
    int wrow0 = row0 + warp * 16;
    for (int i = lane; i < 16 * 16; i += 32) {
        int row = i >> 4;
        int q = i & 15;
        int grow = wrow0 + row;
        if (grow >= N) continue;
        float4 c = ((const float4*)wstage)[i];
        if (RECALL) {
            float a0 = aggx[grow * 3], a1 = aggx[grow * 3 + 1], a2 = aggx[grow * 3 + 2];
            int col = q * 4;
#pragma unroll
            for (int jj = 0; jj < 4; jj++) {
                float add = fmaf(a0, Wx[col + jj],
                             fmaf(a1, Wx[64 + col + jj],
                              fmaf(a2, Wx[128 + col + jj], brv[col + jj])));
                (&c.x)[jj] += add;
            }
            ((float4*)out32)[(size_t)grow * 16 + q] = c;
        }
        uint2 m;
        m.x = f2h(c.x, c.y);
        m.y = f2h(c.z, c.w);
        ((uint2*)out16)[(size_t)grow * 16 + q] = m;
    }
}

// =============== host launch ===============

extern "C" void kernel_launch(void* const* d_in, const int* in_sizes, int n_in,
                              void* d_out, int out_size) {
    const float* x   = (const float*)d_in[0];
    const float* Wp  = (const float*)d_in[1];
    const float* bp  = (const float*)d_in[2];
    const float* Wr  = (const float*)d_in[3];
    const float* br  = (const float*)d_in[4];
    const float* W11 = (const float*)d_in[5];
    const float* b11 = (const float*)d_in[6];
    const float* W12 = (const float*)d_in[7];
    const float* b12 = (const float*)d_in[8];
    const float* W21 = (const float*)d_in[9];
    const float* b21 = (const float*)d_in[10];
    const float* W22 = (const float*)d_in[11];
    const float* b22 = (const float*)d_in[12];
    const float* Wh1 = (const float*)d_in[13];
    const float* bh1 = (const float*)d_in[14];
    const float* Wh2 = (const float*)d_in[15];
    const float* bh2 = (const float*)d_in[16];
    const float* Wh3 = (const float*)d_in[17];
    const float* bh3 = (const float*)d_in[18];
    const int*   ei  = (const int*)d_in[19];

    int N = in_sizes[0] / 3;
    int E = in_sizes[19] / 2;
    const int* esrc = ei;
    const int* edst = ei + E;

    int *zero, *rowoff, *rowend;
    float *dis, *aggx;
    EdgeRec* edges;
    float4 *t4, *u4, *v4;
    uint4 *t16p, *u16p, *v16p, *w16p;
    cudaGetSymbolAddress((void**)&zero, g_zero);
    cudaGetSymbolAddress((void**)&rowoff, g_rowoff);
    cudaGetSymbolAddress((void**)&rowend, g_rowend);
    cudaGetSymbolAddress((void**)&dis, g_dis);
    cudaGetSymbolAddress((void**)&edges, g_edges);
    cudaGetSymbolAddress((void**)&aggx, g_aggx);
    cudaGetSymbolAddress((void**)&t4, g_t);
    cudaGetSymbolAddress((void**)&u4, g_u);
    cudaGetSymbolAddress((void**)&v4, g_v);
    cudaGetSymbolAddress((void**)&t16p, g_t16);
    cudaGetSymbolAddress((void**)&u16p, g_u16);
    cudaGetSymbolAddress((void**)&v16p, g_v16);
    cudaGetSymbolAddress((void**)&w16p, g_w16);
    int* counts = zero;
    int* cursor = zero + NCAP;
    int* total  = zero + 2 * NCAP;
    float* t = (float*)t4;
    float* u = (float*)u4;
    float* v = (float*)v4;
    __half* t16 = (__half*)t16p;
    __half* u16 = (__half*)u16p;
    __half* v16 = (__half*)v16p;
    __half* w16 = (__half*)w16p;
    __half* Wr16   = w16;
    __half* W11_16 = w16 + 4096;
    __half* W12_16 = w16 + 2 * 4096;
    __half* W21_16 = w16 + 3 * 4096;
    __half* W22_16 = w16 + 4 * 4096;

    int nbE = (E + 255) / 256;
    int nbN = (N + 255) / 256;
    int nbWarp = (N + 7) / 8;       // 8 nodes per 256-thread block
    int nbAgg = (N + 15) / 16;      // half-warp agg: 16 nodes per block
    int nbTC = (N + 127) / 128;     // tensor-core mm tiles
    int nbMMH = (N + 95) / 96;      // head mm1 tiles

    // ---- graph setup (5 launches) ----
    cudaMemsetAsync(zero, 0, (size_t)(2 * NCAP + 4) * sizeof(int), 0);
    k_count<<<nbE, 256>>>(edst, E, counts);
    k_setup2<<<nbN, 256>>>(counts, dis, rowoff, rowend, total, N,
                           Wr, W11, W12, W21, W22, w16);
    k_fill<<<nbE, 256>>>(esrc, edst, E, rowoff, cursor, dis, edges);
    k_aggx_proj<<<nbWarp, 256>>>(x, edges, rowoff, rowend, dis,
                                 Wp, bp, aggx, t, t16, N);

    const float* Wrx = Wr + 64 * 64;  // rows 64..66 of Wr (x part)

    // ---- iterations ----
    for (int it = 0; it < ITERS; it++) {
        k_aggv<0, 0, 0><<<nbAgg, 256>>>((uint2*)t16, edges, rowoff, rowend, dis,
                                        nullptr, nullptr, nullptr, (uint2*)v16, N);
        k_mmTC<1><<<nbTC, 256>>>(v16, Wr16, Wrx, br, aggx, t, t16, N);
        // block 1
        k_mmTC<0><<<nbTC, 256>>>(t16, W11_16, nullptr, nullptr, nullptr,
                                 nullptr, u16, N);
        k_aggv<1, 0, 0><<<nbAgg, 256>>>((uint2*)u16, edges, rowoff, rowend, dis,
                                        b11, nullptr, nullptr, (uint2*)v16, N);
        k_mmTC<0><<<nbTC, 256>>>(v16, W12_16, nullptr, nullptr, nullptr,
                                 nullptr, u16, N);
        k_aggv<1, 1, 1><<<nbAgg, 256>>>((uint2*)u16, edges, rowoff, rowend, dis,
                                        b12, t, t, (uint2*)t16, N);
        // block 2
        k_mmTC<0><<<nbTC, 256>>>(t16, W21_16, nullptr, nullptr, nullptr,
                                 nullptr, u16, N);
        k_aggv<1, 0, 0><<<nbAgg, 256>>>((uint2*)u16, edges, rowoff, rowend, dis,
                                        b21, nullptr, nullptr, (uint2*)v16, N);
        k_mmTC<0><<<nbTC, 256>>>(v16, W22_16, nullptr, nullptr, nullptr,
                                 nullptr, u16, N);
        k_aggv<1, 1, 1><<<nbAgg, 256>>>((uint2*)u16, edges, rowoff, rowend, dis,
                                        b22, t, t, (uint2*)t16, N);
    }

    // ---- head (fp32, optimized kernels) ----
    k_mmh1<<<nbMMH, 96>>>(t, Wh1, u, N);
    k_agg32<<<nbWarp, 256>>>(u, edges, rowoff, rowend, dis, bh1, 1, v, N);
    k_mm32x8<<<nbWarp, 256>>>(v, Wh2, u, N);
    k_agg8<<<nbN, 256>>>(u, edges, rowoff, rowend, dis, bh2, 1, v, N);
    k_mm8x2<<<nbN, 256>>>(v, Wh3, u, N);
    k_agg2<<<nbN, 256>>>(u, edges, rowoff, rowend, dis, bh3, (float*)d_out, N);
}